// round 1
// baseline (speedup 1.0000x reference)
#include <cuda_runtime.h>
#include <math.h>

// ----------------------------- problem constants ---------------------------
#define CC   768
#define TT   1024
#define BBATCH 4
#define MM   (BBATCH*TT)      // 4096 tokens
#define NHD  24
#define HSZ  32
#define HP_  32
#define WP_  32
#define C4   (CC/4)           // 192

// one big scratch arena (device-static: allocation-free at runtime)
#define SSLOT 3145728ull                   // 4096*768 floats
__device__ float g_scratch[14ull*SSLOT + 2097152ull];

enum { EP_NONE = 0, EP_TANH = 1, EP_SILU = 2, EP_DECAY = 3 };

// ----------------------------- SGEMM (fp32) --------------------------------
// C[M,N] = ep( A[M,K](lda) @ B[K,N] )  ; assumes M % 128 == 0, K % 16 == 0.
#define GBM 128
#define GBN 64
#define GBK 16

__global__ void __launch_bounds__(256) sgemm_kernel(
    const float* __restrict__ A, int lda,
    const float* __restrict__ B, int N, int K,
    float* __restrict__ C,
    int ep, const float* __restrict__ bias)
{
    __shared__ float As[GBK][GBM];   // transposed A tile
    __shared__ float Bs[GBK][GBN];

    const int tid = threadIdx.x;
    const int bm  = blockIdx.y * GBM;
    const int bn  = blockIdx.x * GBN;

    const int tm = (tid >> 4) * 8;       // 0..120
    const int tn = (tid & 15) * 4;       // 0..60

    const int a_row = tid >> 1;          // 0..127
    const int a_col = (tid & 1) * 8;     // 0 or 8
    const int b_row = tid >> 4;          // 0..15
    const int b_col = (tid & 15) * 4;    // 0..60

    float acc[8][4];
#pragma unroll
    for (int i = 0; i < 8; i++)
#pragma unroll
        for (int j = 0; j < 4; j++) acc[i][j] = 0.f;

    for (int k0 = 0; k0 < K; k0 += GBK) {
        // ---- load A tile (128x16) ----
        const float* Ap = A + (size_t)(bm + a_row) * lda + (k0 + a_col);
        float4 a0 = *(const float4*)(Ap);
        float4 a1 = *(const float4*)(Ap + 4);
        As[a_col + 0][a_row] = a0.x;  As[a_col + 1][a_row] = a0.y;
        As[a_col + 2][a_row] = a0.z;  As[a_col + 3][a_row] = a0.w;
        As[a_col + 4][a_row] = a1.x;  As[a_col + 5][a_row] = a1.y;
        As[a_col + 6][a_row] = a1.z;  As[a_col + 7][a_row] = a1.w;

        // ---- load B tile (16x64) with N guard ----
        {
            int col = bn + b_col;
            const float* Bp = B + (size_t)(k0 + b_row) * N + col;
            float4 bv;
            if (col + 3 < N) {
                bv = *(const float4*)Bp;
            } else {
                bv.x = (col + 0 < N) ? Bp[0] : 0.f;
                bv.y = (col + 1 < N) ? Bp[1] : 0.f;
                bv.z = (col + 2 < N) ? Bp[2] : 0.f;
                bv.w = (col + 3 < N) ? Bp[3] : 0.f;
            }
            Bs[b_row][b_col + 0] = bv.x;  Bs[b_row][b_col + 1] = bv.y;
            Bs[b_row][b_col + 2] = bv.z;  Bs[b_row][b_col + 3] = bv.w;
        }
        __syncthreads();

#pragma unroll
        for (int kk = 0; kk < GBK; kk++) {
            float4 x0 = *(const float4*)&As[kk][tm];
            float4 x1 = *(const float4*)&As[kk][tm + 4];
            float4 y0 = *(const float4*)&Bs[kk][tn];
            float av[8] = {x0.x, x0.y, x0.z, x0.w, x1.x, x1.y, x1.z, x1.w};
            float bv[4] = {y0.x, y0.y, y0.z, y0.w};
#pragma unroll
            for (int i = 0; i < 8; i++)
#pragma unroll
                for (int j = 0; j < 4; j++)
                    acc[i][j] = fmaf(av[i], bv[j], acc[i][j]);
        }
        __syncthreads();
    }

    // ---- epilogue ----
#pragma unroll
    for (int i = 0; i < 8; i++) {
        int row = bm + tm + i;
#pragma unroll
        for (int j = 0; j < 4; j++) {
            int col = bn + tn + j;
            if (col < N) {
                float v = acc[i][j];
                if (ep == EP_TANH)       v = tanhf(v);
                else if (ep == EP_SILU)  v = v / (1.f + expf(-v));
                else if (ep == EP_DECAY) v = expf(-expf(bias[col] + v));
                C[(size_t)row * N + col] = v;
            }
        }
    }
}

// ------------------------- q_shift + maa_x mix ------------------------------
// xx = qshift(x) - x ;  xxx = x + xx * time_maa_x
__global__ void shift_kernel(const float* __restrict__ x,
                             const float* __restrict__ tmx,
                             float* __restrict__ xx,
                             float* __restrict__ xxx)
{
    int idx = blockIdx.x * blockDim.x + threadIdx.x;
    if (idx >= MM * CC) return;
    int c = idx % CC;
    int m = idx / CC;
    int b = m >> 10;
    int t = m & 1023;
    int h = t >> 5;
    int w = t & 31;
    int q = c / C4;
    int sh = h + ((q == 2) ? -1 : (q == 3) ? 1 : 0);
    int sw = w + ((q == 0) ? -1 : (q == 1) ? 1 : 0);
    float xs = 0.f;
    if (sh >= 0 && sh < HP_ && sw >= 0 && sw < WP_)
        xs = x[((size_t)((b << 10) + (sh << 5) + sw)) * CC + c];
    float xv = x[idx];
    float d  = xs - xv;
    xx[idx]  = d;
    xxx[idx] = fmaf(d, tmx[c], xv);
}

// -------------------- mix epilogue: m* -> x{w,k,v,r,g} ----------------------
__global__ void mix_ep_kernel(const float* __restrict__ x,
                              const float* __restrict__ xx,
                              float* __restrict__ b0, float* __restrict__ b1,
                              float* __restrict__ b2, float* __restrict__ b3,
                              float* __restrict__ b4,
                              const float* __restrict__ aw,
                              const float* __restrict__ ak,
                              const float* __restrict__ av,
                              const float* __restrict__ ar,
                              const float* __restrict__ ag)
{
    int idx = blockIdx.x * blockDim.x + threadIdx.x;
    if (idx >= MM * CC) return;
    int c = idx % CC;
    float xv = x[idx];
    float d  = xx[idx];
    b0[idx] = fmaf(d, aw[c] + b0[idx], xv);
    b1[idx] = fmaf(d, ak[c] + b1[idx], xv);
    b2[idx] = fmaf(d, av[c] + b2[idx], xv);
    b3[idx] = fmaf(d, ar[c] + b3[idx], xv);
    b4[idx] = fmaf(d, ag[c] + b4[idx], xv);
}

// ------------------------------ WKV6 scan -----------------------------------
// grid = B*NH blocks; block = 1024 threads. warp = output channel i, lane = j.
// s_{j,i} per thread; y_i = sum_j r_j*(s_{j,i} + u_j*k_j*v_i); s = d_j*s + k_j*v_i
__global__ void __launch_bounds__(1024) wkv_scan_kernel(
    const float* __restrict__ r, const float* __restrict__ k,
    const float* __restrict__ v, const float* __restrict__ d,
    const float* __restrict__ u, float* __restrict__ y)
{
    int head = blockIdx.x;            // b*NH + h
    int b = head / NHD;
    int h = head % NHD;
    int i = threadIdx.x >> 5;         // warp  = output channel
    int j = threadIdx.x & 31;         // lane  = k channel
    float uj = u[h * HSZ + j];
    float s = 0.f;
    size_t base = (size_t)b * TT * CC + h * HSZ;
#pragma unroll 2
    for (int t = 0; t < TT; t++) {
        size_t off = base + (size_t)t * CC;
        float rj = r[off + j];
        float kj = k[off + j];
        float dj = d[off + j];
        float vi = v[off + i];        // broadcast within warp
        float kv = kj * vi;
        float c  = rj * fmaf(uj, kv, s);
        s = fmaf(dj, s, kv);
#pragma unroll
        for (int o = 16; o; o >>= 1)
            c += __shfl_xor_sync(0xffffffffu, c, o);
        if (j == 0) y[off + i] = c;
    }
}

// --------------------------- LayerNorm * gate -------------------------------
__global__ void __launch_bounds__(256) ln_gate_kernel(
    const float* __restrict__ y, const float* __restrict__ g,
    const float* __restrict__ lw, const float* __restrict__ lb,
    float* __restrict__ out)
{
    __shared__ float red[8];
    int m = blockIdx.x;
    int t = threadIdx.x;
    size_t base = (size_t)m * CC;
    float v0 = y[base + t], v1 = y[base + t + 256], v2 = y[base + t + 512];
    float s = v0 + v1 + v2;
#pragma unroll
    for (int o = 16; o; o >>= 1) s += __shfl_xor_sync(0xffffffffu, s, o);
    if ((t & 31) == 0) red[t >> 5] = s;
    __syncthreads();
    float tot = red[0] + red[1] + red[2] + red[3] + red[4] + red[5] + red[6] + red[7];
    float mu = tot * (1.f / CC);
    float d0 = v0 - mu, d1 = v1 - mu, d2 = v2 - mu;
    float q = d0 * d0 + d1 * d1 + d2 * d2;
#pragma unroll
    for (int o = 16; o; o >>= 1) q += __shfl_xor_sync(0xffffffffu, q, o);
    __syncthreads();
    if ((t & 31) == 0) red[t >> 5] = q;
    __syncthreads();
    float var = (red[0] + red[1] + red[2] + red[3] + red[4] + red[5] + red[6] + red[7]) * (1.f / CC);
    float inv = rsqrtf(var + 1e-5f);
    out[base + t]       = (d0 * inv * lw[t]       + lb[t])       * g[base + t];
    out[base + t + 256] = (d1 * inv * lw[t + 256] + lb[t + 256]) * g[base + t + 256];
    out[base + t + 512] = (d2 * inv * lw[t + 512] + lb[t + 512]) * g[base + t + 512];
}

// ------------------------------- launcher -----------------------------------
extern "C" void kernel_launch(void* const* d_in, const int* in_sizes, int n_in,
                              void* d_out, int out_size)
{
    const float* x    = (const float*)d_in[0];
    const float* tmx  = (const float*)d_in[1];
    const float* tmw  = (const float*)d_in[2];
    const float* tmk  = (const float*)d_in[3];
    const float* tmv  = (const float*)d_in[4];
    const float* tmr  = (const float*)d_in[5];
    const float* tmg  = (const float*)d_in[6];
    const float* w1   = (const float*)d_in[7];   // (768,160)
    const float* w2   = (const float*)d_in[8];   // (5,32,768)
    const float* tdec = (const float*)d_in[9];   // (768)
    const float* dw1  = (const float*)d_in[10];  // (768,64)
    const float* dw2  = (const float*)d_in[11];  // (64,768)
    const float* faaa = (const float*)d_in[12];  // (24,32)
    const float* W_r  = (const float*)d_in[13];
    const float* W_k  = (const float*)d_in[14];
    const float* W_v  = (const float*)d_in[15];
    const float* W_g  = (const float*)d_in[16];
    const float* W_o  = (const float*)d_in[17];
    const float* lnw  = (const float*)d_in[18];
    const float* lnb  = (const float*)d_in[19];
    float* out = (float*)d_out;

    float* buf = nullptr;
    cudaGetSymbolAddress((void**)&buf, g_scratch);

    float* xx  = buf;
    float* xxx = buf + 1 * SSLOT;
    float* m0  = buf + 2 * SSLOT;   // -> xw
    float* m1  = buf + 3 * SSLOT;   // -> xk
    float* m2  = buf + 4 * SSLOT;   // -> xv
    float* m3  = buf + 5 * SSLOT;   // -> xr
    float* m4  = buf + 6 * SSLOT;   // -> xg
    float* rr  = buf + 7 * SSLOT;
    float* kk  = buf + 8 * SSLOT;
    float* vv  = buf + 9 * SSLOT;
    float* gg  = buf + 10 * SSLOT;
    float* dd  = buf + 11 * SSLOT;
    float* yy  = buf + 12 * SSLOT;
    float* G1  = buf + 13 * SSLOT;              // 4096 x 160
    float* ww  = buf + 13 * SSLOT + 1048576;    // 4096 x 64
    float* ln  = xx;                            // reuse xx for LN*g output

    const int EW_BLOCKS = (MM * CC + 255) / 256;

    // 1) q-shift + maa_x mix
    shift_kernel<<<EW_BLOCKS, 256>>>(x, tmx, xx, xxx);

    // 2) G1 = tanh(xxx @ w1)   (4096 x 160)
    {
        dim3 grid((160 + GBN - 1) / GBN, MM / GBM);
        sgemm_kernel<<<grid, 256>>>(xxx, CC, w1, 160, CC, G1, EP_TANH, nullptr);
    }

    // 3) 5 mix GEMMs (K=32)
    {
        dim3 grid(CC / GBN, MM / GBM);
        float* mouts[5] = {m0, m1, m2, m3, m4};
        for (int q = 0; q < 5; q++)
            sgemm_kernel<<<grid, 256>>>(G1 + q * 32, 160,
                                        w2 + (size_t)q * 32 * CC, CC, 32,
                                        mouts[q], EP_NONE, nullptr);
    }

    // 4) mix epilogue -> xw,xk,xv,xr,xg (in place)
    mix_ep_kernel<<<EW_BLOCKS, 256>>>(x, xx, m0, m1, m2, m3, m4,
                                      tmw, tmk, tmv, tmr, tmg);

    // 5) projections
    {
        dim3 grid(CC / GBN, MM / GBM);
        sgemm_kernel<<<grid, 256>>>(m3, CC, W_r, CC, CC, rr, EP_NONE, nullptr);
        sgemm_kernel<<<grid, 256>>>(m1, CC, W_k, CC, CC, kk, EP_NONE, nullptr);
        sgemm_kernel<<<grid, 256>>>(m2, CC, W_v, CC, CC, vv, EP_NONE, nullptr);
        sgemm_kernel<<<grid, 256>>>(m4, CC, W_g, CC, CC, gg, EP_SILU, nullptr);
        dim3 gridd(64 / GBN, MM / GBM);
        sgemm_kernel<<<gridd, 256>>>(m0, CC, dw1, 64, CC, ww, EP_TANH, nullptr);
        sgemm_kernel<<<grid, 256>>>(ww, 64, dw2, CC, 64, dd, EP_DECAY, tdec);
    }

    // 6) WKV6 scan
    wkv_scan_kernel<<<BBATCH * NHD, 1024>>>(rr, kk, vv, dd, faaa, yy);

    // 7) LayerNorm * gate
    ln_gate_kernel<<<MM, 256>>>(yy, gg, lnw, lnb, ln);

    // 8) output projection
    {
        dim3 grid(CC / GBN, MM / GBM);
        sgemm_kernel<<<grid, 256>>>(ln, CC, W_o, CC, CC, out, EP_NONE, nullptr);
    }

    (void)in_sizes; (void)n_in; (void)out_size;
}

// round 2
// speedup vs baseline: 2.1398x; 2.1398x over previous
#include <cuda_runtime.h>
#include <math.h>
#include <stdint.h>

// ----------------------------- problem constants ---------------------------
#define CC   768
#define TT   1024
#define BBATCH 4
#define MM   (BBATCH*TT)      // 4096 tokens
#define NHD  24
#define HSZ  32
#define HP_  32
#define WP_  32
#define C4   (CC/4)           // 192
#define CL   32               // wkv chunk length

// one big scratch arena (device-static: allocation-free at runtime)
#define SSLOT 3145728ull                   // 4096*768 floats
__device__ float g_scratch[14ull*SSLOT + 2097152ull];

enum { EP_NONE = 0, EP_TANH = 1, EP_SILU = 2, EP_EXPW = 3 };

// ----------------------------- TF32 helpers --------------------------------
__device__ __forceinline__ float f2tf32(float x) {
    uint32_t r;
    asm("cvt.rna.tf32.f32 %0, %1;" : "=r"(r) : "f"(x));
    return __uint_as_float(r);
}

__device__ __forceinline__ void mma_tf32(float acc[4], const uint32_t a[4],
                                         const uint32_t b[2]) {
    asm volatile(
        "mma.sync.aligned.m16n8k8.row.col.f32.tf32.tf32.f32 "
        "{%0,%1,%2,%3}, {%4,%5,%6,%7}, {%8,%9}, {%0,%1,%2,%3};"
        : "+f"(acc[0]), "+f"(acc[1]), "+f"(acc[2]), "+f"(acc[3])
        : "r"(a[0]), "r"(a[1]), "r"(a[2]), "r"(a[3]), "r"(b[0]), "r"(b[1]));
}

// -------------------------- TF32 MMA GEMM ----------------------------------
// C[M,N] = ep( A[M,K](lda) @ B[K,N](ldb=N) ); M%128==0, K%32==0. N guarded.
// Batched along blockIdx.z via element offsets a_z/b_z/c_z.
#define TBM 128
#define TBN 64
#define TBK 32

__global__ void __launch_bounds__(256) mma_gemm_kernel(
    const float* __restrict__ A, int lda, long long a_z,
    const float* __restrict__ B, long long b_z,
    float* __restrict__ Cp, long long c_z,
    int N, int K, int ep, const float* __restrict__ bias)
{
    A  += (size_t)blockIdx.z * a_z;
    B  += (size_t)blockIdx.z * b_z;
    Cp += (size_t)blockIdx.z * c_z;

    __shared__ float As[TBM][TBK + 4];   // 128 x 36
    __shared__ float Bs[TBK][TBN + 8];   // 32 x 72

    const int tid  = threadIdx.x;
    const int wid  = tid >> 5;
    const int lane = tid & 31;
    const int gr   = lane >> 2;          // 0..7
    const int gc   = lane & 3;           // 0..3
    const int wm   = (wid & 3) * 32;     // warp m offset within tile
    const int wn   = (wid >> 2) * 32;    // warp n offset within tile
    const int bm   = blockIdx.y * TBM;
    const int bn   = blockIdx.x * TBN;

    const int arow = tid >> 1;           // 0..127
    const int acol = (tid & 1) * 16;     // 0 or 16
    const int brow = tid >> 3;           // 0..31
    const int bcol = (tid & 7) * 8;      // 0..56

    float acc[2][4][4];
#pragma unroll
    for (int mi = 0; mi < 2; mi++)
#pragma unroll
        for (int ni = 0; ni < 4; ni++)
#pragma unroll
            for (int c = 0; c < 4; c++) acc[mi][ni][c] = 0.f;

    for (int k0 = 0; k0 < K; k0 += TBK) {
        // A tile
        const float* Ap = A + (size_t)(bm + arow) * lda + k0 + acol;
#pragma unroll
        for (int s = 0; s < 4; s++) {
            float4 v4 = *(const float4*)(Ap + 4 * s);
            As[arow][acol + 4*s + 0] = f2tf32(v4.x);
            As[arow][acol + 4*s + 1] = f2tf32(v4.y);
            As[arow][acol + 4*s + 2] = f2tf32(v4.z);
            As[arow][acol + 4*s + 3] = f2tf32(v4.w);
        }
        // B tile (N-guarded)
        const float* Bp = B + (size_t)(k0 + brow) * N + bn + bcol;
#pragma unroll
        for (int s = 0; s < 2; s++) {
            int col = bn + bcol + 4 * s;
            float4 v4;
            if (col + 3 < N) {
                v4 = *(const float4*)(Bp + 4 * s);
            } else {
                v4.x = (col + 0 < N) ? Bp[4*s + 0] : 0.f;
                v4.y = (col + 1 < N) ? Bp[4*s + 1] : 0.f;
                v4.z = (col + 2 < N) ? Bp[4*s + 2] : 0.f;
                v4.w = (col + 3 < N) ? Bp[4*s + 3] : 0.f;
            }
            Bs[brow][bcol + 4*s + 0] = f2tf32(v4.x);
            Bs[brow][bcol + 4*s + 1] = f2tf32(v4.y);
            Bs[brow][bcol + 4*s + 2] = f2tf32(v4.z);
            Bs[brow][bcol + 4*s + 3] = f2tf32(v4.w);
        }
        __syncthreads();

#pragma unroll
        for (int kk = 0; kk < TBK; kk += 8) {
            uint32_t af[2][4], bf[4][2];
#pragma unroll
            for (int mi = 0; mi < 2; mi++) {
                af[mi][0] = __float_as_uint(As[wm + mi*16 + gr    ][kk + gc    ]);
                af[mi][1] = __float_as_uint(As[wm + mi*16 + gr + 8][kk + gc    ]);
                af[mi][2] = __float_as_uint(As[wm + mi*16 + gr    ][kk + gc + 4]);
                af[mi][3] = __float_as_uint(As[wm + mi*16 + gr + 8][kk + gc + 4]);
            }
#pragma unroll
            for (int ni = 0; ni < 4; ni++) {
                bf[ni][0] = __float_as_uint(Bs[kk + gc    ][wn + ni*8 + gr]);
                bf[ni][1] = __float_as_uint(Bs[kk + gc + 4][wn + ni*8 + gr]);
            }
#pragma unroll
            for (int mi = 0; mi < 2; mi++)
#pragma unroll
                for (int ni = 0; ni < 4; ni++)
                    mma_tf32(acc[mi][ni], af[mi], bf[ni]);
        }
        __syncthreads();
    }

    // epilogue
#pragma unroll
    for (int mi = 0; mi < 2; mi++) {
#pragma unroll
        for (int ni = 0; ni < 4; ni++) {
#pragma unroll
            for (int c = 0; c < 4; c++) {
                int row = bm + wm + mi*16 + gr + ((c >> 1) ? 8 : 0);
                int col = bn + wn + ni*8 + 2*gc + (c & 1);
                if (col < N) {
                    float v = acc[mi][ni][c];
                    if      (ep == EP_TANH) v = tanhf(v);
                    else if (ep == EP_SILU) v = v / (1.f + expf(-v));
                    else if (ep == EP_EXPW) v = expf(bias[col] + v);
                    Cp[(size_t)row * N + col] = v;
                }
            }
        }
    }
}

// ------------------------- q_shift + maa_x mix (float4) ---------------------
__global__ void shift_kernel(const float* __restrict__ x,
                             const float* __restrict__ tmx,
                             float* __restrict__ xx,
                             float* __restrict__ xxx)
{
    int idx = blockIdx.x * blockDim.x + threadIdx.x;   // over MM*192
    if (idx >= MM * (CC/4)) return;
    int c4i = idx % (CC/4);
    int m   = idx / (CC/4);
    int c   = c4i * 4;
    int b = m >> 10;
    int t = m & 1023;
    int hh = t >> 5;
    int w  = t & 31;
    int q  = c / C4;
    int sh = hh + ((q == 2) ? -1 : (q == 3) ? 1 : 0);
    int sw = w  + ((q == 0) ? -1 : (q == 1) ? 1 : 0);
    float4 xs = make_float4(0.f, 0.f, 0.f, 0.f);
    if (sh >= 0 && sh < HP_ && sw >= 0 && sw < WP_)
        xs = *(const float4*)(x + ((size_t)((b << 10) + (sh << 5) + sw)) * CC + c);
    float4 xv = ((const float4*)x)[idx];
    float4 tm = *(const float4*)(tmx + c);
    float4 d, o;
    d.x = xs.x - xv.x; d.y = xs.y - xv.y; d.z = xs.z - xv.z; d.w = xs.w - xv.w;
    o.x = fmaf(d.x, tm.x, xv.x); o.y = fmaf(d.y, tm.y, xv.y);
    o.z = fmaf(d.z, tm.z, xv.z); o.w = fmaf(d.w, tm.w, xv.w);
    ((float4*)xx)[idx]  = d;
    ((float4*)xxx)[idx] = o;
}

// -------------------- mix epilogue: m* -> x{w,k,v,r,g} (float4) -------------
__global__ void mix_ep_kernel(const float* __restrict__ x,
                              const float* __restrict__ xx,
                              float* __restrict__ b0, float* __restrict__ b1,
                              float* __restrict__ b2, float* __restrict__ b3,
                              float* __restrict__ b4,
                              const float* __restrict__ aw,
                              const float* __restrict__ ak,
                              const float* __restrict__ av,
                              const float* __restrict__ ar,
                              const float* __restrict__ ag)
{
    int idx = blockIdx.x * blockDim.x + threadIdx.x;
    if (idx >= MM * (CC/4)) return;
    int c = (idx % (CC/4)) * 4;
    float4 xv = ((const float4*)x)[idx];
    float4 d  = ((const float4*)xx)[idx];
#define APPLY(bp, ap) { \
    float4 m4 = ((const float4*)bp)[idx]; \
    float4 a4 = *(const float4*)(ap + c); \
    m4.x = fmaf(d.x, a4.x + m4.x, xv.x); \
    m4.y = fmaf(d.y, a4.y + m4.y, xv.y); \
    m4.z = fmaf(d.z, a4.z + m4.z, xv.z); \
    m4.w = fmaf(d.w, a4.w + m4.w, xv.w); \
    ((float4*)bp)[idx] = m4; }
    APPLY(b0, aw) APPLY(b1, ak) APPLY(b2, av) APPLY(b3, ar) APPLY(b4, ag)
#undef APPLY
}

// ----------------------------- chunked WKV6 ---------------------------------
// One block per (b,h). L=32 chunks; diagonal-decay chunked linear attention:
//   logB (exclusive cumsum of -ew), R~ = r*exp(logB_excl), Kt = k*exp(-logB_incl)
//   att[t,tau] = R~_t . Kt_tau  (tau<t), diag = r.(u*k), 0 above
//   Y = att@V + R~@S ;  S = exp(-cum_end)*S + Kh^T@V,  Kh = k*exp(cum - cum_end)
__global__ void __launch_bounds__(256) wkv_chunk_kernel(
    const float* __restrict__ r, const float* __restrict__ k,
    const float* __restrict__ v, const float* __restrict__ ew,
    const float* __restrict__ u, float* __restrict__ y)
{
    __shared__ float sr[CL][36], sk[CL][36], sv[CL][36], se[CL][36];
    __shared__ float scum[CL][36], sKtT[HSZ][36], satt[CL][36], sS[HSZ][36];
    __shared__ float sdiag[CL], scend[HSZ], su[HSZ];

    const int head = blockIdx.x;
    const int b = head / NHD, h = head % NHD;
    const int tid = threadIdx.x;
    const int tld = tid >> 3;           // 0..31  (row)
    const int jld = (tid & 7) << 2;     // 0,4,...,28 (col base)

    if (tid < HSZ) su[tid] = u[h * HSZ + tid];
    for (int z = tid; z < HSZ * 36; z += 256) ((float*)sS)[z] = 0.f;

    const size_t base = (size_t)b * TT * CC + (size_t)h * HSZ;
    __syncthreads();

    for (int c0 = 0; c0 < TT; c0 += CL) {
        // ---- load tiles ----
        size_t g = base + (size_t)(c0 + tld) * CC + jld;
        float4 r4 = *(const float4*)(r + g);
        float4 k4 = *(const float4*)(k + g);
        float4 v4 = *(const float4*)(v + g);
        float4 e4 = *(const float4*)(ew + g);
        sr[tld][jld+0]=r4.x; sr[tld][jld+1]=r4.y; sr[tld][jld+2]=r4.z; sr[tld][jld+3]=r4.w;
        sk[tld][jld+0]=k4.x; sk[tld][jld+1]=k4.y; sk[tld][jld+2]=k4.z; sk[tld][jld+3]=k4.w;
        sv[tld][jld+0]=v4.x; sv[tld][jld+1]=v4.y; sv[tld][jld+2]=v4.z; sv[tld][jld+3]=v4.w;
        se[tld][jld+0]=e4.x; se[tld][jld+1]=e4.y; se[tld][jld+2]=e4.z; se[tld][jld+3]=e4.w;
        __syncthreads();

        // ---- cumsum (warp0) + diag (warp1) ----
        if (tid < HSZ) {
            float acc = 0.f;
#pragma unroll
            for (int t = 0; t < CL; t++) { acc += se[t][tid]; scum[t][tid] = acc; }
            scend[tid] = acc;
        } else if (tid < 2 * HSZ) {
            int t = tid - HSZ;
            float dg = 0.f;
#pragma unroll
            for (int j = 0; j < HSZ; j++) dg += sr[t][j] * su[j] * sk[t][j];
            sdiag[t] = dg;
        }
        __syncthreads();

        // ---- transform ----
#pragma unroll
        for (int e = 0; e < 4; e++) {
            int j = jld + e;
            float cum = scum[tld][j];
            float ev  = se[tld][j];
            float rw  = sr[tld][j];
            float kw  = sk[tld][j];
            sr[tld][j]   = rw * expf(ev - cum);          // r * exp(logB_excl)
            sKtT[j][tld] = kw * expf(cum);               // k * exp(-logB_incl)
            scum[tld][j] = kw * expf(cum - scend[j]);    // Kh
        }
        __syncthreads();

        // ---- att = R~ @ Kt^T, masked ----
        {
            const int t = tld, t4 = jld;
            float a0 = 0.f, a1 = 0.f, a2 = 0.f, a3 = 0.f;
#pragma unroll
            for (int j = 0; j < HSZ; j++) {
                float rt = sr[t][j];
                float4 kt = *(const float4*)&sKtT[j][t4];
                a0 = fmaf(rt, kt.x, a0); a1 = fmaf(rt, kt.y, a1);
                a2 = fmaf(rt, kt.z, a2); a3 = fmaf(rt, kt.w, a3);
            }
            float dv = sdiag[t];
            satt[t][t4+0] = (t4+0 < t) ? a0 : ((t4+0 == t) ? dv : 0.f);
            satt[t][t4+1] = (t4+1 < t) ? a1 : ((t4+1 == t) ? dv : 0.f);
            satt[t][t4+2] = (t4+2 < t) ? a2 : ((t4+2 == t) ? dv : 0.f);
            satt[t][t4+3] = (t4+3 < t) ? a3 : ((t4+3 == t) ? dv : 0.f);
        }
        __syncthreads();

        // ---- Y = att @ V + R~ @ S ----
        {
            const int t = tld, i4 = jld;
            float4 acc = make_float4(0.f, 0.f, 0.f, 0.f);
#pragma unroll
            for (int tau = 0; tau < CL; tau++) {
                float at = satt[t][tau];
                float4 vv = *(const float4*)&sv[tau][i4];
                acc.x = fmaf(at, vv.x, acc.x); acc.y = fmaf(at, vv.y, acc.y);
                acc.z = fmaf(at, vv.z, acc.z); acc.w = fmaf(at, vv.w, acc.w);
            }
#pragma unroll
            for (int j = 0; j < HSZ; j++) {
                float rt = sr[t][j];
                float4 sj = *(const float4*)&sS[j][i4];
                acc.x = fmaf(rt, sj.x, acc.x); acc.y = fmaf(rt, sj.y, acc.y);
                acc.z = fmaf(rt, sj.z, acc.z); acc.w = fmaf(rt, sj.w, acc.w);
            }
            *(float4*)(y + base + (size_t)(c0 + t) * CC + i4) = acc;
        }
        __syncthreads();

        // ---- S = exp(-cum_end) * S + Kh^T @ V ----
        {
            const int j = tld, i4 = jld;
            float dend = expf(-scend[j]);
            float4 s = *(const float4*)&sS[j][i4];
            s.x *= dend; s.y *= dend; s.z *= dend; s.w *= dend;
#pragma unroll
            for (int tau = 0; tau < CL; tau++) {
                float kh = scum[tau][j];
                float4 vv = *(const float4*)&sv[tau][i4];
                s.x = fmaf(kh, vv.x, s.x); s.y = fmaf(kh, vv.y, s.y);
                s.z = fmaf(kh, vv.z, s.z); s.w = fmaf(kh, vv.w, s.w);
            }
            *(float4*)&sS[j][i4] = s;
        }
        __syncthreads();
    }
}

// --------------------------- LayerNorm * gate -------------------------------
__global__ void __launch_bounds__(256) ln_gate_kernel(
    const float* __restrict__ y, const float* __restrict__ g,
    const float* __restrict__ lw, const float* __restrict__ lb,
    float* __restrict__ out)
{
    __shared__ float red[8];
    int m = blockIdx.x;
    int t = threadIdx.x;
    size_t base = (size_t)m * CC;
    float v0 = y[base + t], v1 = y[base + t + 256], v2 = y[base + t + 512];
    float s = v0 + v1 + v2;
#pragma unroll
    for (int o = 16; o; o >>= 1) s += __shfl_xor_sync(0xffffffffu, s, o);
    if ((t & 31) == 0) red[t >> 5] = s;
    __syncthreads();
    float tot = red[0]+red[1]+red[2]+red[3]+red[4]+red[5]+red[6]+red[7];
    float mu = tot * (1.f / CC);
    float d0 = v0 - mu, d1 = v1 - mu, d2 = v2 - mu;
    float q = d0*d0 + d1*d1 + d2*d2;
#pragma unroll
    for (int o = 16; o; o >>= 1) q += __shfl_xor_sync(0xffffffffu, q, o);
    __syncthreads();
    if ((t & 31) == 0) red[t >> 5] = q;
    __syncthreads();
    float var = (red[0]+red[1]+red[2]+red[3]+red[4]+red[5]+red[6]+red[7]) * (1.f / CC);
    float inv = rsqrtf(var + 1e-5f);
    out[base + t]       = (d0 * inv * lw[t]       + lb[t])       * g[base + t];
    out[base + t + 256] = (d1 * inv * lw[t + 256] + lb[t + 256]) * g[base + t + 256];
    out[base + t + 512] = (d2 * inv * lw[t + 512] + lb[t + 512]) * g[base + t + 512];
}

// ------------------------------- launcher -----------------------------------
extern "C" void kernel_launch(void* const* d_in, const int* in_sizes, int n_in,
                              void* d_out, int out_size)
{
    const float* x    = (const float*)d_in[0];
    const float* tmx  = (const float*)d_in[1];
    const float* tmw  = (const float*)d_in[2];
    const float* tmk  = (const float*)d_in[3];
    const float* tmv  = (const float*)d_in[4];
    const float* tmr  = (const float*)d_in[5];
    const float* tmg  = (const float*)d_in[6];
    const float* w1   = (const float*)d_in[7];   // (768,160)
    const float* w2   = (const float*)d_in[8];   // (5,32,768)
    const float* tdec = (const float*)d_in[9];   // (768)
    const float* dw1  = (const float*)d_in[10];  // (768,64)
    const float* dw2  = (const float*)d_in[11];  // (64,768)
    const float* faaa = (const float*)d_in[12];  // (24,32)
    const float* W_r  = (const float*)d_in[13];
    const float* W_k  = (const float*)d_in[14];
    const float* W_v  = (const float*)d_in[15];
    const float* W_g  = (const float*)d_in[16];
    const float* W_o  = (const float*)d_in[17];
    const float* lnw  = (const float*)d_in[18];
    const float* lnb  = (const float*)d_in[19];
    float* out = (float*)d_out;

    float* buf = nullptr;
    cudaGetSymbolAddress((void**)&buf, g_scratch);

    float* xx  = buf;
    float* xxx = buf + 1 * SSLOT;
    float* m0  = buf + 2 * SSLOT;   // -> xw   (m0..m4 contiguous for z-batch)
    float* m1  = buf + 3 * SSLOT;   // -> xk
    float* m2  = buf + 4 * SSLOT;   // -> xv
    float* m3  = buf + 5 * SSLOT;   // -> xr
    float* m4  = buf + 6 * SSLOT;   // -> xg
    float* rr  = buf + 7 * SSLOT;
    float* kk  = buf + 8 * SSLOT;
    float* vv  = buf + 9 * SSLOT;
    float* gg  = buf + 10 * SSLOT;
    float* eww = buf + 11 * SSLOT;  // exp(w)
    float* yy  = buf + 12 * SSLOT;
    float* G1  = buf + 13 * SSLOT;              // 4096 x 160
    float* ww  = buf + 13 * SSLOT + 1048576;    // 4096 x 64
    float* ln  = xx;                            // reuse xx for LN*g output

    const int EW4 = (MM * (CC/4) + 255) / 256;

    // 1) q-shift + maa_x mix
    shift_kernel<<<EW4, 256>>>(x, tmx, xx, xxx);

    // 2) G1 = tanh(xxx @ w1)   (4096 x 160)
    mma_gemm_kernel<<<dim3(3, 32, 1), 256>>>(xxx, CC, 0, w1, 0, G1, 0,
                                             160, 768, EP_TANH, nullptr);

    // 3) 5 mix GEMMs, batched over z (K=32)
    mma_gemm_kernel<<<dim3(12, 32, 5), 256>>>(G1, 160, 32, w2, 32*768,
                                              m0, (long long)SSLOT,
                                              768, 32, EP_NONE, nullptr);

    // 4) mix epilogue -> xw,xk,xv,xr,xg (in place)
    mix_ep_kernel<<<EW4, 256>>>(x, xx, m0, m1, m2, m3, m4,
                                tmw, tmk, tmv, tmr, tmg);

    // 5) projections
    {
        dim3 grid(12, 32);
        mma_gemm_kernel<<<grid, 256>>>(m3, CC, 0, W_r, 0, rr, 0, 768, 768, EP_NONE, nullptr);
        mma_gemm_kernel<<<grid, 256>>>(m1, CC, 0, W_k, 0, kk, 0, 768, 768, EP_NONE, nullptr);
        mma_gemm_kernel<<<grid, 256>>>(m2, CC, 0, W_v, 0, vv, 0, 768, 768, EP_NONE, nullptr);
        mma_gemm_kernel<<<grid, 256>>>(m4, CC, 0, W_g, 0, gg, 0, 768, 768, EP_SILU, nullptr);
        mma_gemm_kernel<<<dim3(1, 32), 256>>>(m0, CC, 0, dw1, 0, ww, 0, 64, 768, EP_TANH, nullptr);
        mma_gemm_kernel<<<grid, 256>>>(ww, 64, 0, dw2, 0, eww, 0, 768, 64, EP_EXPW, tdec);
    }

    // 6) chunked WKV6
    wkv_chunk_kernel<<<BBATCH * NHD, 256>>>(rr, kk, vv, eww, faaa, yy);

    // 7) LayerNorm * gate
    ln_gate_kernel<<<MM, 256>>>(yy, gg, lnw, lnb, ln);

    // 8) output projection
    mma_gemm_kernel<<<dim3(12, 32), 256>>>(ln, CC, 0, W_o, 0, out, 0,
                                           768, 768, EP_NONE, nullptr);

    (void)in_sizes; (void)n_in; (void)out_size;
}

// round 3
// speedup vs baseline: 2.2060x; 1.0309x over previous
#include <cuda_runtime.h>
#include <math.h>
#include <stdint.h>

// ----------------------------- problem constants ---------------------------
#define CC   768
#define TT   1024
#define BBATCH 4
#define MM   (BBATCH*TT)      // 4096 tokens
#define NHD  24
#define HSZ  32
#define HP_  32
#define WP_  32
#define C4   (CC/4)           // 192
#define CL   32               // wkv chunk length

// one big scratch arena (device-static: allocation-free at runtime)
#define SSLOT 3145728ull                   // 4096*768 floats
__device__ float g_scratch[14ull*SSLOT + 2097152ull];

enum { EP_NONE = 0, EP_TANH = 1, EP_SILU = 2, EP_EXPW = 3, EP_MIX = 4 };

// ----------------------------- TF32 helpers --------------------------------
__device__ __forceinline__ float f2tf32(float x) {
    uint32_t r;
    asm("cvt.rna.tf32.f32 %0, %1;" : "=r"(r) : "f"(x));
    return __uint_as_float(r);
}

__device__ __forceinline__ void mma_tf32(float acc[4], const uint32_t a[4],
                                         const uint32_t b[2]) {
    asm volatile(
        "mma.sync.aligned.m16n8k8.row.col.f32.tf32.tf32.f32 "
        "{%0,%1,%2,%3}, {%4,%5,%6,%7}, {%8,%9}, {%0,%1,%2,%3};"
        : "+f"(acc[0]), "+f"(acc[1]), "+f"(acc[2]), "+f"(acc[3])
        : "r"(a[0]), "r"(a[1]), "r"(a[2]), "r"(a[3]), "r"(b[0]), "r"(b[1]));
}

// -------------------------- grouped TF32 MMA GEMM ---------------------------
// Per z: C[M,N] = ep( A[M,K](lda) @ B[K,N] ). M%128==0, K%16==0, N guarded.
struct GArgs {
    const float* A[5];
    const float* B[5];
    float*       C[5];
    const float* tm[5];     // EP_MIX per-z channel vector
    int ep[5];
    int N[5];
    int lda[5];
    int K;
    const float* x;         // EP_MIX
    const float* xx;        // EP_MIX
    const float* bias;      // EP_EXPW
};

#define TBM 128
#define TBN 128
#define TBK 16

#define LDG_TILE(k0)                                                          \
    {                                                                         \
        const float* Ap = A + (size_t)(bm + arow) * lda + (k0) + acol;        \
        ra0 = *(const float4*)Ap;                                             \
        ra1 = *(const float4*)(Ap + 4);                                       \
        const float* Bp = B + (size_t)((k0) + brow) * N + bn + bcol;          \
        int cbase = bn + bcol;                                                \
        if (cbase + 7 < N) {                                                  \
            rb0 = *(const float4*)Bp;                                         \
            rb1 = *(const float4*)(Bp + 4);                                   \
        } else {                                                              \
            rb0.x = (cbase+0<N)?Bp[0]:0.f; rb0.y = (cbase+1<N)?Bp[1]:0.f;     \
            rb0.z = (cbase+2<N)?Bp[2]:0.f; rb0.w = (cbase+3<N)?Bp[3]:0.f;     \
            rb1.x = (cbase+4<N)?Bp[4]:0.f; rb1.y = (cbase+5<N)?Bp[5]:0.f;     \
            rb1.z = (cbase+6<N)?Bp[6]:0.f; rb1.w = (cbase+7<N)?Bp[7]:0.f;     \
        }                                                                     \
    }

#define STS_TILE(bq)                                                          \
    {                                                                         \
        As[bq][arow][acol+0]=f2tf32(ra0.x); As[bq][arow][acol+1]=f2tf32(ra0.y);\
        As[bq][arow][acol+2]=f2tf32(ra0.z); As[bq][arow][acol+3]=f2tf32(ra0.w);\
        As[bq][arow][acol+4]=f2tf32(ra1.x); As[bq][arow][acol+5]=f2tf32(ra1.y);\
        As[bq][arow][acol+6]=f2tf32(ra1.z); As[bq][arow][acol+7]=f2tf32(ra1.w);\
        Bs[bq][brow][bcol+0]=f2tf32(rb0.x); Bs[bq][brow][bcol+1]=f2tf32(rb0.y);\
        Bs[bq][brow][bcol+2]=f2tf32(rb0.z); Bs[bq][brow][bcol+3]=f2tf32(rb0.w);\
        Bs[bq][brow][bcol+4]=f2tf32(rb1.x); Bs[bq][brow][bcol+5]=f2tf32(rb1.y);\
        Bs[bq][brow][bcol+6]=f2tf32(rb1.z); Bs[bq][brow][bcol+7]=f2tf32(rb1.w);\
    }

__global__ void __launch_bounds__(256, 2) gemm_kernel(GArgs ga)
{
    __shared__ float As[2][TBM][20];
    __shared__ float Bs[2][TBK][136];

    const int z = blockIdx.z;
    const float* __restrict__ A = ga.A[z];
    const float* __restrict__ B = ga.B[z];
    float* __restrict__ C = ga.C[z];
    const int N   = ga.N[z];
    const int lda = ga.lda[z];
    const int K   = ga.K;
    const int ep  = ga.ep[z];

    const int bn = blockIdx.x * TBN;
    if (bn >= N) return;
    const int bm = blockIdx.y * TBM;

    const int tid  = threadIdx.x;
    const int lane = tid & 31;
    const int wid  = tid >> 5;
    const int gr = lane >> 2, gc = lane & 3;
    const int wm = (wid & 3) * 32;
    const int wn = (wid >> 2) * 64;

    const int arow = tid >> 1;
    const int acol = (tid & 1) * 8;
    const int brow = tid >> 4;
    const int bcol = (tid & 15) * 8;

    float acc[2][8][4];
#pragma unroll
    for (int mi = 0; mi < 2; mi++)
#pragma unroll
        for (int ni = 0; ni < 8; ni++)
#pragma unroll
            for (int c = 0; c < 4; c++) acc[mi][ni][c] = 0.f;

    float4 ra0, ra1, rb0, rb1;

    LDG_TILE(0)
    STS_TILE(0)
    __syncthreads();

    const int niter = K / TBK;
    for (int it = 0; it < niter; it++) {
        const int bq = it & 1;
        if (it + 1 < niter) LDG_TILE((it + 1) * TBK)

#pragma unroll
        for (int kk = 0; kk < TBK; kk += 8) {
            uint32_t af[2][4], bf[8][2];
#pragma unroll
            for (int mi = 0; mi < 2; mi++) {
                int r0 = wm + mi * 16 + gr;
                af[mi][0] = __float_as_uint(As[bq][r0    ][kk + gc    ]);
                af[mi][1] = __float_as_uint(As[bq][r0 + 8][kk + gc    ]);
                af[mi][2] = __float_as_uint(As[bq][r0    ][kk + gc + 4]);
                af[mi][3] = __float_as_uint(As[bq][r0 + 8][kk + gc + 4]);
            }
#pragma unroll
            for (int ni = 0; ni < 8; ni++) {
                int col = wn + ni * 8 + gr;
                bf[ni][0] = __float_as_uint(Bs[bq][kk + gc    ][col]);
                bf[ni][1] = __float_as_uint(Bs[bq][kk + gc + 4][col]);
            }
#pragma unroll
            for (int mi = 0; mi < 2; mi++)
#pragma unroll
                for (int ni = 0; ni < 8; ni++)
                    mma_tf32(acc[mi][ni], af[mi], bf[ni]);
        }

        if (it + 1 < niter) STS_TILE(bq ^ 1)
        __syncthreads();
    }

    // epilogue
    const float* tmv = ga.tm[z];
#pragma unroll
    for (int mi = 0; mi < 2; mi++) {
#pragma unroll
        for (int ni = 0; ni < 8; ni++) {
#pragma unroll
            for (int c = 0; c < 4; c++) {
                int row = bm + wm + mi * 16 + gr + ((c >> 1) << 3);
                int col = bn + wn + ni * 8 + 2 * gc + (c & 1);
                if (col < N) {
                    float v = acc[mi][ni][c];
                    if      (ep == EP_TANH) v = tanhf(v);
                    else if (ep == EP_SILU) v = v / (1.f + expf(-v));
                    else if (ep == EP_EXPW) v = expf(ga.bias[col] + v);
                    else if (ep == EP_MIX) {
                        size_t ix = (size_t)row * CC + col;
                        v = fmaf(ga.xx[ix], tmv[col] + v, ga.x[ix]);
                    }
                    C[(size_t)row * N + col] = v;
                }
            }
        }
    }
}

// ------------------------- q_shift + maa_x mix (float4) ---------------------
__global__ void shift_kernel(const float* __restrict__ x,
                             const float* __restrict__ tmx,
                             float* __restrict__ xx,
                             float* __restrict__ xxx)
{
    int idx = blockIdx.x * blockDim.x + threadIdx.x;   // over MM*192
    if (idx >= MM * (CC/4)) return;
    int c4i = idx % (CC/4);
    int m   = idx / (CC/4);
    int c   = c4i * 4;
    int b = m >> 10;
    int t = m & 1023;
    int hh = t >> 5;
    int w  = t & 31;
    int q  = c / C4;
    int sh = hh + ((q == 2) ? -1 : (q == 3) ? 1 : 0);
    int sw = w  + ((q == 0) ? -1 : (q == 1) ? 1 : 0);
    float4 xs = make_float4(0.f, 0.f, 0.f, 0.f);
    if (sh >= 0 && sh < HP_ && sw >= 0 && sw < WP_)
        xs = *(const float4*)(x + ((size_t)((b << 10) + (sh << 5) + sw)) * CC + c);
    float4 xv = ((const float4*)x)[idx];
    float4 tm = *(const float4*)(tmx + c);
    float4 d, o;
    d.x = xs.x - xv.x; d.y = xs.y - xv.y; d.z = xs.z - xv.z; d.w = xs.w - xv.w;
    o.x = fmaf(d.x, tm.x, xv.x); o.y = fmaf(d.y, tm.y, xv.y);
    o.z = fmaf(d.z, tm.z, xv.z); o.w = fmaf(d.w, tm.w, xv.w);
    ((float4*)xx)[idx]  = d;
    ((float4*)xxx)[idx] = o;
}

// ----------------------------- chunked WKV6 ---------------------------------
__global__ void __launch_bounds__(256) wkv_chunk_kernel(
    const float* __restrict__ r, const float* __restrict__ k,
    const float* __restrict__ v, const float* __restrict__ ew,
    const float* __restrict__ u, float* __restrict__ y)
{
    __shared__ float sr[CL][36], sk[CL][36], sv[CL][36], se[CL][36];
    __shared__ float scum[CL][36], sKtT[HSZ][36], satt[CL][36], sS[HSZ][36];
    __shared__ float sdiag[CL], scend[HSZ], su[HSZ];

    const int head = blockIdx.x;
    const int b = head / NHD, h = head % NHD;
    const int tid  = threadIdx.x;
    const int lane = tid & 31;
    const int wid  = tid >> 5;
    const int tld = tid >> 3;           // 0..31  (row)
    const int jld = (tid & 7) << 2;     // 0,4,...,28 (col base)

    if (tid < HSZ) su[tid] = u[h * HSZ + tid];
    for (int zz = tid; zz < HSZ * 36; zz += 256) ((float*)sS)[zz] = 0.f;

    const size_t base = (size_t)b * TT * CC + (size_t)h * HSZ;

    // preload chunk 0
    size_t g0 = base + (size_t)tld * CC + jld;
    float4 r4 = *(const float4*)(r  + g0);
    float4 k4 = *(const float4*)(k  + g0);
    float4 v4 = *(const float4*)(v  + g0);
    float4 e4 = *(const float4*)(ew + g0);
    __syncthreads();

    for (int c0 = 0; c0 < TT; c0 += CL) {
        // ---- store prefetched tiles ----
        *(float4*)&sr[tld][jld] = r4;
        *(float4*)&sk[tld][jld] = k4;
        *(float4*)&sv[tld][jld] = v4;
        *(float4*)&se[tld][jld] = e4;
        __syncthreads();

        // ---- cumsum over t (warp scan, warp wid owns j = wid*4..+3) ----
#pragma unroll
        for (int q = 0; q < 4; q++) {
            int j = wid * 4 + q;
            float vv = se[lane][j];
#pragma unroll
            for (int off = 1; off < 32; off <<= 1) {
                float nb = __shfl_up_sync(0xffffffffu, vv, off);
                if (lane >= off) vv += nb;
            }
            scum[lane][j] = vv;
            if (lane == 31) scend[j] = vv;
        }
        // ---- diag: dg[t] = sum_j r*u*k, 8-lane tree ----
        {
            float p = 0.f;
#pragma unroll
            for (int e = 0; e < 4; e++)
                p += sr[tld][jld + e] * su[jld + e] * sk[tld][jld + e];
            p += __shfl_xor_sync(0xffffffffu, p, 1);
            p += __shfl_xor_sync(0xffffffffu, p, 2);
            p += __shfl_xor_sync(0xffffffffu, p, 4);
            if ((lane & 7) == 0) sdiag[tld] = p;
        }
        __syncthreads();

        // ---- transform ----
#pragma unroll
        for (int e = 0; e < 4; e++) {
            int j = jld + e;
            float cum = scum[tld][j];
            float ev  = se[tld][j];
            float rw  = sr[tld][j];
            float kw  = sk[tld][j];
            sr[tld][j]   = rw * expf(ev - cum);          // r * exp(logB_excl)
            sKtT[j][tld] = kw * expf(cum);               // k * exp(-logB_incl)
            scum[tld][j] = kw * expf(cum - scend[j]);    // Kh
        }
        __syncthreads();

        // ---- att = R~ @ Kt^T, masked ----
        {
            const int t = tld, t4 = jld;
            float a0 = 0.f, a1 = 0.f, a2 = 0.f, a3 = 0.f;
#pragma unroll
            for (int j = 0; j < HSZ; j++) {
                float rt = sr[t][j];
                float4 kt = *(const float4*)&sKtT[j][t4];
                a0 = fmaf(rt, kt.x, a0); a1 = fmaf(rt, kt.y, a1);
                a2 = fmaf(rt, kt.z, a2); a3 = fmaf(rt, kt.w, a3);
            }
            float dv = sdiag[t];
            satt[t][t4+0] = (t4+0 < t) ? a0 : ((t4+0 == t) ? dv : 0.f);
            satt[t][t4+1] = (t4+1 < t) ? a1 : ((t4+1 == t) ? dv : 0.f);
            satt[t][t4+2] = (t4+2 < t) ? a2 : ((t4+2 == t) ? dv : 0.f);
            satt[t][t4+3] = (t4+3 < t) ? a3 : ((t4+3 == t) ? dv : 0.f);
        }
        __syncthreads();

        // ---- prefetch next chunk while att/Y compute ----
        if (c0 + CL < TT) {
            size_t gn = base + (size_t)(c0 + CL + tld) * CC + jld;
            r4 = *(const float4*)(r  + gn);
            k4 = *(const float4*)(k  + gn);
            v4 = *(const float4*)(v  + gn);
            e4 = *(const float4*)(ew + gn);
        }

        // ---- Y = att @ V + R~ @ S ----
        {
            const int t = tld, i4 = jld;
            float4 acc = make_float4(0.f, 0.f, 0.f, 0.f);
#pragma unroll
            for (int tau = 0; tau < CL; tau++) {
                float at = satt[t][tau];
                float4 vv = *(const float4*)&sv[tau][i4];
                acc.x = fmaf(at, vv.x, acc.x); acc.y = fmaf(at, vv.y, acc.y);
                acc.z = fmaf(at, vv.z, acc.z); acc.w = fmaf(at, vv.w, acc.w);
            }
#pragma unroll
            for (int j = 0; j < HSZ; j++) {
                float rt = sr[t][j];
                float4 sj = *(const float4*)&sS[j][i4];
                acc.x = fmaf(rt, sj.x, acc.x); acc.y = fmaf(rt, sj.y, acc.y);
                acc.z = fmaf(rt, sj.z, acc.z); acc.w = fmaf(rt, sj.w, acc.w);
            }
            *(float4*)(y + base + (size_t)(c0 + t) * CC + i4) = acc;
        }
        __syncthreads();

        // ---- S = exp(-cum_end) * S + Kh^T @ V ----
        {
            const int j = tld, i4 = jld;
            float dend = expf(-scend[j]);
            float4 s = *(const float4*)&sS[j][i4];
            s.x *= dend; s.y *= dend; s.z *= dend; s.w *= dend;
#pragma unroll
            for (int tau = 0; tau < CL; tau++) {
                float kh = scum[tau][j];
                float4 vv = *(const float4*)&sv[tau][i4];
                s.x = fmaf(kh, vv.x, s.x); s.y = fmaf(kh, vv.y, s.y);
                s.z = fmaf(kh, vv.z, s.z); s.w = fmaf(kh, vv.w, s.w);
            }
            *(float4*)&sS[j][i4] = s;
        }
        __syncthreads();
    }
}

// --------------------------- LayerNorm * gate -------------------------------
__global__ void __launch_bounds__(256) ln_gate_kernel(
    const float* __restrict__ y, const float* __restrict__ g,
    const float* __restrict__ lw, const float* __restrict__ lb,
    float* __restrict__ out)
{
    __shared__ float red[8];
    int m = blockIdx.x;
    int t = threadIdx.x;
    size_t base = (size_t)m * CC;
    float v0 = y[base + t], v1 = y[base + t + 256], v2 = y[base + t + 512];
    float s = v0 + v1 + v2;
#pragma unroll
    for (int o = 16; o; o >>= 1) s += __shfl_xor_sync(0xffffffffu, s, o);
    if ((t & 31) == 0) red[t >> 5] = s;
    __syncthreads();
    float tot = red[0]+red[1]+red[2]+red[3]+red[4]+red[5]+red[6]+red[7];
    float mu = tot * (1.f / CC);
    float d0 = v0 - mu, d1 = v1 - mu, d2 = v2 - mu;
    float q = d0*d0 + d1*d1 + d2*d2;
#pragma unroll
    for (int o = 16; o; o >>= 1) q += __shfl_xor_sync(0xffffffffu, q, o);
    __syncthreads();
    if ((t & 31) == 0) red[t >> 5] = q;
    __syncthreads();
    float var = (red[0]+red[1]+red[2]+red[3]+red[4]+red[5]+red[6]+red[7]) * (1.f / CC);
    float inv = rsqrtf(var + 1e-5f);
    out[base + t]       = (d0 * inv * lw[t]       + lb[t])       * g[base + t];
    out[base + t + 256] = (d1 * inv * lw[t + 256] + lb[t + 256]) * g[base + t + 256];
    out[base + t + 512] = (d2 * inv * lw[t + 512] + lb[t + 512]) * g[base + t + 512];
}

// ------------------------------- launcher -----------------------------------
extern "C" void kernel_launch(void* const* d_in, const int* in_sizes, int n_in,
                              void* d_out, int out_size)
{
    const float* x    = (const float*)d_in[0];
    const float* tmx  = (const float*)d_in[1];
    const float* tmw  = (const float*)d_in[2];
    const float* tmk  = (const float*)d_in[3];
    const float* tmv  = (const float*)d_in[4];
    const float* tmr  = (const float*)d_in[5];
    const float* tmg  = (const float*)d_in[6];
    const float* w1   = (const float*)d_in[7];   // (768,160)
    const float* w2   = (const float*)d_in[8];   // (5,32,768)
    const float* tdec = (const float*)d_in[9];   // (768)
    const float* dw1  = (const float*)d_in[10];  // (768,64)
    const float* dw2  = (const float*)d_in[11];  // (64,768)
    const float* faaa = (const float*)d_in[12];  // (24,32)
    const float* W_r  = (const float*)d_in[13];
    const float* W_k  = (const float*)d_in[14];
    const float* W_v  = (const float*)d_in[15];
    const float* W_g  = (const float*)d_in[16];
    const float* W_o  = (const float*)d_in[17];
    const float* lnw  = (const float*)d_in[18];
    const float* lnb  = (const float*)d_in[19];
    float* out = (float*)d_out;

    float* buf = nullptr;
    cudaGetSymbolAddress((void**)&buf, g_scratch);

    float* xx  = buf;
    float* xxx = buf + 1 * SSLOT;
    float* m0  = buf + 2 * SSLOT;   // -> xw
    float* m1  = buf + 3 * SSLOT;   // -> xk
    float* m2  = buf + 4 * SSLOT;   // -> xv
    float* m3  = buf + 5 * SSLOT;   // -> xr
    float* m4  = buf + 6 * SSLOT;   // -> xg
    float* rr  = buf + 7 * SSLOT;
    float* kk  = buf + 8 * SSLOT;
    float* vv  = buf + 9 * SSLOT;
    float* gg  = buf + 10 * SSLOT;
    float* eww = buf + 11 * SSLOT;  // exp(w)
    float* yy  = buf + 12 * SSLOT;
    float* G1  = buf + 13 * SSLOT;              // 4096 x 160
    float* ww  = buf + 13 * SSLOT + 1048576;    // 4096 x 64
    float* ln  = xx;                            // reuse xx for LN*g output

    const int EW4 = (MM * (CC/4) + 255) / 256;

    // 1) q-shift + maa_x mix
    shift_kernel<<<EW4, 256>>>(x, tmx, xx, xxx);

    // 2) G1 = tanh(xxx @ w1)   (4096 x 160)
    {
        GArgs a = {};
        a.A[0] = xxx; a.B[0] = w1; a.C[0] = G1;
        a.ep[0] = EP_TANH; a.N[0] = 160; a.lda[0] = CC; a.K = CC;
        gemm_kernel<<<dim3(2, 32, 1), 256>>>(a);
    }

    // 3) 5 mix GEMMs (K=32), mix epilogue fused: m_z = x + xx*(tm_z + G1_z@w2_z)
    {
        GArgs a = {};
        float* mouts[5] = {m0, m1, m2, m3, m4};
        const float* tms[5] = {tmw, tmk, tmv, tmr, tmg};
        for (int q = 0; q < 5; q++) {
            a.A[q] = G1 + q * 32;
            a.B[q] = w2 + (size_t)q * 32 * CC;
            a.C[q] = mouts[q];
            a.tm[q] = tms[q];
            a.ep[q] = EP_MIX; a.N[q] = CC; a.lda[q] = 160;
        }
        a.K = 32; a.x = x; a.xx = xx;
        gemm_kernel<<<dim3(6, 32, 5), 256>>>(a);
    }

    // 4) grouped projections: r,k,v,g (N=768) + dw1 (N=64), all K=768
    {
        GArgs a = {};
        a.A[0] = m3; a.B[0] = W_r; a.C[0] = rr; a.ep[0] = EP_NONE; a.N[0] = CC; a.lda[0] = CC;
        a.A[1] = m1; a.B[1] = W_k; a.C[1] = kk; a.ep[1] = EP_NONE; a.N[1] = CC; a.lda[1] = CC;
        a.A[2] = m2; a.B[2] = W_v; a.C[2] = vv; a.ep[2] = EP_NONE; a.N[2] = CC; a.lda[2] = CC;
        a.A[3] = m4; a.B[3] = W_g; a.C[3] = gg; a.ep[3] = EP_SILU; a.N[3] = CC; a.lda[3] = CC;
        a.A[4] = m0; a.B[4] = dw1; a.C[4] = ww; a.ep[4] = EP_TANH; a.N[4] = 64; a.lda[4] = CC;
        a.K = CC;
        gemm_kernel<<<dim3(6, 32, 5), 256>>>(a);
    }

    // 5) eww = exp(tdec + ww @ dw2)
    {
        GArgs a = {};
        a.A[0] = ww; a.B[0] = dw2; a.C[0] = eww;
        a.ep[0] = EP_EXPW; a.N[0] = CC; a.lda[0] = 64; a.K = 64;
        a.bias = tdec;
        gemm_kernel<<<dim3(6, 32, 1), 256>>>(a);
    }

    // 6) chunked WKV6
    wkv_chunk_kernel<<<BBATCH * NHD, 256>>>(rr, kk, vv, eww, faaa, yy);

    // 7) LayerNorm * gate
    ln_gate_kernel<<<MM, 256>>>(yy, gg, lnw, lnb, ln);

    // 8) output projection
    {
        GArgs a = {};
        a.A[0] = ln; a.B[0] = W_o; a.C[0] = out;
        a.ep[0] = EP_NONE; a.N[0] = CC; a.lda[0] = CC; a.K = CC;
        gemm_kernel<<<dim3(6, 32, 1), 256>>>(a);
    }

    (void)in_sizes; (void)n_in; (void)out_size;
}

// round 4
// speedup vs baseline: 2.4785x; 1.1235x over previous
#include <cuda_runtime.h>
#include <math.h>
#include <stdint.h>

// ----------------------------- problem constants ---------------------------
#define CC   768
#define TT   1024
#define BBATCH 4
#define MM   (BBATCH*TT)      // 4096 tokens
#define NHD  24
#define HSZ  32
#define HP_  32
#define WP_  32
#define C4   (CC/4)           // 192
#define CL   32               // wkv chunk length

// one big scratch arena (device-static: allocation-free at runtime)
#define SSLOT 3145728ull                   // 4096*768 floats
__device__ float g_scratch[16ull*SSLOT];

enum { EP_NONE = 0, EP_TANH = 1, EP_SILU = 2, EP_EXPW = 3, EP_MIX = 4 };

// ----------------------------- TF32 helpers --------------------------------
__device__ __forceinline__ float f2tf32(float x) {
    uint32_t r;
    asm("cvt.rna.tf32.f32 %0, %1;" : "=r"(r) : "f"(x));
    return __uint_as_float(r);
}

__device__ __forceinline__ void mma_tf32(float acc[4], const uint32_t a[4],
                                         const uint32_t b0, const uint32_t b1) {
    asm volatile(
        "mma.sync.aligned.m16n8k8.row.col.f32.tf32.tf32.f32 "
        "{%0,%1,%2,%3}, {%4,%5,%6,%7}, {%8,%9}, {%0,%1,%2,%3};"
        : "+f"(acc[0]), "+f"(acc[1]), "+f"(acc[2]), "+f"(acc[3])
        : "r"(a[0]), "r"(a[1]), "r"(a[2]), "r"(a[3]), "r"(b0), "r"(b1));
}

#define LDSM4(d0, d1, d2, d3, addr)                                           \
    asm volatile("ldmatrix.sync.aligned.m8n8.x4.shared.b16 {%0,%1,%2,%3}, [%4];" \
                 : "=r"(d0), "=r"(d1), "=r"(d2), "=r"(d3) : "r"(addr));

// --------------------- weight transpose + tf32 pre-round --------------------
// dst[Np][K] = tf32( src[K][N] )^T, zero-padded rows for n >= N.
#define NTR 13
struct TArgs {
    const float* src[NTR];
    float*       dst[NTR];
    int K[NTR];
    int N[NTR];
    int Np[NTR];
};

__global__ void transpose_kernel(TArgs ta)
{
    __shared__ float tile[32][33];
    const int z = blockIdx.z;
    const int K = ta.K[z], N = ta.N[z], Np = ta.Np[z];
    const int x0 = blockIdx.x * 32;   // n
    const int y0 = blockIdx.y * 32;   // k
    if (x0 >= Np || y0 >= K) return;
    const float* src = ta.src[z];
    float* dst = ta.dst[z];
    const int tx = threadIdx.x, ty = threadIdx.y;
#pragma unroll
    for (int j = 0; j < 4; j++) {
        int k = y0 + ty + 8 * j;
        int n = x0 + tx;
        float v = (n < N) ? src[(size_t)k * N + n] : 0.f;
        tile[ty + 8 * j][tx] = f2tf32(v);
    }
    __syncthreads();
#pragma unroll
    for (int j = 0; j < 4; j++) {
        int n = x0 + ty + 8 * j;
        int k = y0 + tx;
        dst[(size_t)n * K + k] = tile[tx][ty + 8 * j];
    }
}

// -------------------------- grouped TF32 MMA GEMM ---------------------------
// Per z: C[M,N] = ep( A[M,K](lda) @ Bt[n][k]^T ). M%128==0, K%16==0.
// Bt is the pre-transposed, tf32-rounded weight: Bt[Np][K], Np multiple of 128.
struct GArgs {
    const float* A[5];
    const float* B[5];     // transposed weights [Np][K]
    float*       C[5];
    const float* tm[5];    // EP_MIX per-z channel vector
    int ep[5];
    int N[5];
    int lda[5];
    int K;
    const float* x;        // EP_MIX
    const float* xx;       // EP_MIX
    const float* bias;     // EP_EXPW
};

#define TBM 128
#define TBN 128
#define TBK 16

#define LDG_TILE(k0)                                                         \
    {                                                                        \
        const float* Ap = A + (size_t)(bm + arow) * lda + (k0) + acol;       \
        ra0 = *(const float4*)Ap;                                            \
        ra1 = *(const float4*)(Ap + 4);                                      \
        const float* Bp = B + (size_t)(bn + brow) * K + (k0) + bcol;         \
        rb0 = *(const float4*)Bp;                                            \
        rb1 = *(const float4*)(Bp + 4);                                      \
    }

#define STS_TILE(bq)                                                         \
    {                                                                        \
        float4 c0 = make_float4(f2tf32(ra0.x), f2tf32(ra0.y),                \
                                f2tf32(ra0.z), f2tf32(ra0.w));               \
        float4 c1 = make_float4(f2tf32(ra1.x), f2tf32(ra1.y),                \
                                f2tf32(ra1.z), f2tf32(ra1.w));               \
        *(float4*)&As[bq][arow][acol]     = c0;                              \
        *(float4*)&As[bq][arow][acol + 4] = c1;                              \
        *(float4*)&Bs[bq][brow][bcol]     = rb0;                             \
        *(float4*)&Bs[bq][brow][bcol + 4] = rb1;                             \
    }

__global__ void __launch_bounds__(256, 2) gemm_kernel(GArgs ga)
{
    __shared__ float As[2][TBM][20];     // [m][k] tf32
    __shared__ float Bs[2][TBN][20];     // [n][k] tf32 (already rounded)

    const int z = blockIdx.z;
    const float* __restrict__ A = ga.A[z];
    const float* __restrict__ B = ga.B[z];
    float* __restrict__ C = ga.C[z];
    const int N   = ga.N[z];
    const int lda = ga.lda[z];
    const int K   = ga.K;
    const int ep  = ga.ep[z];

    const int bn = blockIdx.x * TBN;
    if (bn >= N) return;
    const int bm = blockIdx.y * TBM;

    const int tid  = threadIdx.x;
    const int lane = tid & 31;
    const int wid  = tid >> 5;
    const int gr = lane >> 2, gc = lane & 3;
    const int wm = (wid & 3) * 32;
    const int wn = (wid >> 2) * 64;

    const int arow = tid >> 1;
    const int acol = (tid & 1) * 8;
    const int brow = arow;               // n row for B
    const int bcol = acol;               // k chunk for B

    // ldmatrix lane addresses (bytes)
    const int p  = lane >> 3;
    const int pr = lane & 7;
    uint32_t as_u = (uint32_t)__cvta_generic_to_shared(&As[0][0][0]);
    uint32_t bs_u = (uint32_t)__cvta_generic_to_shared(&Bs[0][0][0]);
    const uint32_t a_lane = as_u + (uint32_t)((wm + (p & 1) * 8 + pr) * 80 + (p >> 1) * 16);
    const uint32_t b_lane = bs_u + (uint32_t)((wn + (p >> 1) * 8 + pr) * 80 + (p & 1) * 16);

    float acc[2][8][4];
#pragma unroll
    for (int mi = 0; mi < 2; mi++)
#pragma unroll
        for (int ni = 0; ni < 8; ni++)
#pragma unroll
            for (int c = 0; c < 4; c++) acc[mi][ni][c] = 0.f;

    float4 ra0, ra1, rb0, rb1;

    LDG_TILE(0)
    STS_TILE(0)
    __syncthreads();

    const int niter = K / TBK;
    for (int it = 0; it < niter; it++) {
        const int bq = it & 1;
        const uint32_t abase = a_lane + bq * 10240;
        const uint32_t bbase = b_lane + bq * 10240;
        if (it + 1 < niter) LDG_TILE((it + 1) * TBK)

#pragma unroll
        for (int kk = 0; kk < TBK; kk += 8) {
            uint32_t af[2][4], bf[4][4];
#pragma unroll
            for (int mi = 0; mi < 2; mi++)
                LDSM4(af[mi][0], af[mi][1], af[mi][2], af[mi][3],
                      abase + mi * 1280 + kk * 4)
#pragma unroll
            for (int P = 0; P < 4; P++)
                LDSM4(bf[P][0], bf[P][1], bf[P][2], bf[P][3],
                      bbase + P * 1280 + kk * 4)
#pragma unroll
            for (int mi = 0; mi < 2; mi++)
#pragma unroll
                for (int ni = 0; ni < 8; ni++)
                    mma_tf32(acc[mi][ni], af[mi],
                             bf[ni >> 1][(ni & 1) * 2],
                             bf[ni >> 1][(ni & 1) * 2 + 1]);
        }

        if (it + 1 < niter) STS_TILE(bq ^ 1)
        __syncthreads();
    }

    // epilogue (pairs c0/c1 are adjacent columns -> float2 stores)
    const float* tmv = ga.tm[z];
#pragma unroll
    for (int mi = 0; mi < 2; mi++) {
#pragma unroll
        for (int ni = 0; ni < 8; ni++) {
#pragma unroll
            for (int cp = 0; cp < 2; cp++) {
                int row = bm + wm + mi * 16 + gr + cp * 8;
                int col = bn + wn + ni * 8 + 2 * gc;
                float v0 = acc[mi][ni][cp * 2];
                float v1 = acc[mi][ni][cp * 2 + 1];
                if (col + 1 < N) {
                    if (ep == EP_TANH) { v0 = tanhf(v0); v1 = tanhf(v1); }
                    else if (ep == EP_SILU) {
                        v0 = v0 / (1.f + expf(-v0));
                        v1 = v1 / (1.f + expf(-v1));
                    } else if (ep == EP_EXPW) {
                        v0 = expf(ga.bias[col] + v0);
                        v1 = expf(ga.bias[col + 1] + v1);
                    } else if (ep == EP_MIX) {
                        size_t ix = (size_t)row * CC + col;
                        v0 = fmaf(ga.xx[ix],     tmv[col]     + v0, ga.x[ix]);
                        v1 = fmaf(ga.xx[ix + 1], tmv[col + 1] + v1, ga.x[ix + 1]);
                    }
                    *(float2*)&C[(size_t)row * N + col] = make_float2(v0, v1);
                } else if (col < N) {
                    if (ep == EP_TANH) v0 = tanhf(v0);
                    else if (ep == EP_SILU) v0 = v0 / (1.f + expf(-v0));
                    else if (ep == EP_EXPW) v0 = expf(ga.bias[col] + v0);
                    else if (ep == EP_MIX) {
                        size_t ix = (size_t)row * CC + col;
                        v0 = fmaf(ga.xx[ix], tmv[col] + v0, ga.x[ix]);
                    }
                    C[(size_t)row * N + col] = v0;
                }
            }
        }
    }
}

// ------------------------- q_shift + maa_x mix (float4) ---------------------
__global__ void shift_kernel(const float* __restrict__ x,
                             const float* __restrict__ tmx,
                             float* __restrict__ xx,
                             float* __restrict__ xxx)
{
    int idx = blockIdx.x * blockDim.x + threadIdx.x;   // over MM*192
    if (idx >= MM * (CC/4)) return;
    int c4i = idx % (CC/4);
    int m   = idx / (CC/4);
    int c   = c4i * 4;
    int b = m >> 10;
    int t = m & 1023;
    int hh = t >> 5;
    int w  = t & 31;
    int q  = c / C4;
    int sh = hh + ((q == 2) ? -1 : (q == 3) ? 1 : 0);
    int sw = w  + ((q == 0) ? -1 : (q == 1) ? 1 : 0);
    float4 xs = make_float4(0.f, 0.f, 0.f, 0.f);
    if (sh >= 0 && sh < HP_ && sw >= 0 && sw < WP_)
        xs = *(const float4*)(x + ((size_t)((b << 10) + (sh << 5) + sw)) * CC + c);
    float4 xv = ((const float4*)x)[idx];
    float4 tm = *(const float4*)(tmx + c);
    float4 d, o;
    d.x = xs.x - xv.x; d.y = xs.y - xv.y; d.z = xs.z - xv.z; d.w = xs.w - xv.w;
    o.x = fmaf(d.x, tm.x, xv.x); o.y = fmaf(d.y, tm.y, xv.y);
    o.z = fmaf(d.z, tm.z, xv.z); o.w = fmaf(d.w, tm.w, xv.w);
    ((float4*)xx)[idx]  = d;
    ((float4*)xxx)[idx] = o;
}

// ----------------------------- chunked WKV6 ---------------------------------
__global__ void __launch_bounds__(256) wkv_chunk_kernel(
    const float* __restrict__ r, const float* __restrict__ k,
    const float* __restrict__ v, const float* __restrict__ ew,
    const float* __restrict__ u, float* __restrict__ y)
{
    __shared__ float sr[CL][36], sk[CL][36], sv[CL][36], se[CL][36];
    __shared__ float scum[CL][36], sKtT[HSZ][36], satt[CL][36], sS[HSZ][36];
    __shared__ float sdiag[CL], scend[HSZ], su[HSZ];

    const int head = blockIdx.x;
    const int b = head / NHD, h = head % NHD;
    const int tid  = threadIdx.x;
    const int lane = tid & 31;
    const int wid  = tid >> 5;
    const int tld = tid >> 3;           // 0..31  (row)
    const int jld = (tid & 7) << 2;     // 0,4,...,28 (col base)

    if (tid < HSZ) su[tid] = u[h * HSZ + tid];
    for (int zz = tid; zz < HSZ * 36; zz += 256) ((float*)sS)[zz] = 0.f;

    const size_t base = (size_t)b * TT * CC + (size_t)h * HSZ;

    // preload chunk 0
    size_t g0 = base + (size_t)tld * CC + jld;
    float4 r4 = *(const float4*)(r  + g0);
    float4 k4 = *(const float4*)(k  + g0);
    float4 v4 = *(const float4*)(v  + g0);
    float4 e4 = *(const float4*)(ew + g0);
    __syncthreads();

    for (int c0 = 0; c0 < TT; c0 += CL) {
        *(float4*)&sr[tld][jld] = r4;
        *(float4*)&sk[tld][jld] = k4;
        *(float4*)&sv[tld][jld] = v4;
        *(float4*)&se[tld][jld] = e4;
        __syncthreads();

        // cumsum over t (warp scan; warp wid owns j = wid*4..+3)
#pragma unroll
        for (int q = 0; q < 4; q++) {
            int j = wid * 4 + q;
            float vv = se[lane][j];
#pragma unroll
            for (int off = 1; off < 32; off <<= 1) {
                float nb = __shfl_up_sync(0xffffffffu, vv, off);
                if (lane >= off) vv += nb;
            }
            scum[lane][j] = vv;
            if (lane == 31) scend[j] = vv;
        }
        // diag: dg[t] = sum_j r*u*k (8-lane tree)
        {
            float pp = 0.f;
#pragma unroll
            for (int e = 0; e < 4; e++)
                pp += sr[tld][jld + e] * su[jld + e] * sk[tld][jld + e];
            pp += __shfl_xor_sync(0xffffffffu, pp, 1);
            pp += __shfl_xor_sync(0xffffffffu, pp, 2);
            pp += __shfl_xor_sync(0xffffffffu, pp, 4);
            if ((lane & 7) == 0) sdiag[tld] = pp;
        }
        __syncthreads();

        // transform
#pragma unroll
        for (int e = 0; e < 4; e++) {
            int j = jld + e;
            float cum = scum[tld][j];
            float ev  = se[tld][j];
            float rw  = sr[tld][j];
            float kw  = sk[tld][j];
            sr[tld][j]   = rw * expf(ev - cum);
            sKtT[j][tld] = kw * expf(cum);
            scum[tld][j] = kw * expf(cum - scend[j]);
        }
        __syncthreads();

        // att = R~ @ Kt^T, masked
        {
            const int t = tld, t4 = jld;
            float a0 = 0.f, a1 = 0.f, a2 = 0.f, a3 = 0.f;
#pragma unroll
            for (int j = 0; j < HSZ; j++) {
                float rt = sr[t][j];
                float4 kt = *(const float4*)&sKtT[j][t4];
                a0 = fmaf(rt, kt.x, a0); a1 = fmaf(rt, kt.y, a1);
                a2 = fmaf(rt, kt.z, a2); a3 = fmaf(rt, kt.w, a3);
            }
            float dv = sdiag[t];
            satt[t][t4+0] = (t4+0 < t) ? a0 : ((t4+0 == t) ? dv : 0.f);
            satt[t][t4+1] = (t4+1 < t) ? a1 : ((t4+1 == t) ? dv : 0.f);
            satt[t][t4+2] = (t4+2 < t) ? a2 : ((t4+2 == t) ? dv : 0.f);
            satt[t][t4+3] = (t4+3 < t) ? a3 : ((t4+3 == t) ? dv : 0.f);
        }
        __syncthreads();

        // prefetch next chunk
        if (c0 + CL < TT) {
            size_t gn = base + (size_t)(c0 + CL + tld) * CC + jld;
            r4 = *(const float4*)(r  + gn);
            k4 = *(const float4*)(k  + gn);
            v4 = *(const float4*)(v  + gn);
            e4 = *(const float4*)(ew + gn);
        }

        // Y = att @ V + R~ @ S
        {
            const int t = tld, i4 = jld;
            float4 acc = make_float4(0.f, 0.f, 0.f, 0.f);
#pragma unroll
            for (int tau = 0; tau < CL; tau++) {
                float at = satt[t][tau];
                float4 vv = *(const float4*)&sv[tau][i4];
                acc.x = fmaf(at, vv.x, acc.x); acc.y = fmaf(at, vv.y, acc.y);
                acc.z = fmaf(at, vv.z, acc.z); acc.w = fmaf(at, vv.w, acc.w);
            }
#pragma unroll
            for (int j = 0; j < HSZ; j++) {
                float rt = sr[t][j];
                float4 sj = *(const float4*)&sS[j][i4];
                acc.x = fmaf(rt, sj.x, acc.x); acc.y = fmaf(rt, sj.y, acc.y);
                acc.z = fmaf(rt, sj.z, acc.z); acc.w = fmaf(rt, sj.w, acc.w);
            }
            *(float4*)(y + base + (size_t)(c0 + t) * CC + i4) = acc;
        }
        __syncthreads();

        // S = exp(-cum_end) * S + Kh^T @ V
        {
            const int j = tld, i4 = jld;
            float dend = expf(-scend[j]);
            float4 s = *(const float4*)&sS[j][i4];
            s.x *= dend; s.y *= dend; s.z *= dend; s.w *= dend;
#pragma unroll
            for (int tau = 0; tau < CL; tau++) {
                float kh = scum[tau][j];
                float4 vv = *(const float4*)&sv[tau][i4];
                s.x = fmaf(kh, vv.x, s.x); s.y = fmaf(kh, vv.y, s.y);
                s.z = fmaf(kh, vv.z, s.z); s.w = fmaf(kh, vv.w, s.w);
            }
            *(float4*)&sS[j][i4] = s;
        }
        __syncthreads();
    }
}

// --------------------------- LayerNorm * gate -------------------------------
__global__ void __launch_bounds__(256) ln_gate_kernel(
    const float* __restrict__ y, const float* __restrict__ g,
    const float* __restrict__ lw, const float* __restrict__ lb,
    float* __restrict__ out)
{
    __shared__ float red[8];
    int m = blockIdx.x;
    int t = threadIdx.x;
    size_t base = (size_t)m * CC;
    float v0 = y[base + t], v1 = y[base + t + 256], v2 = y[base + t + 512];
    float s = v0 + v1 + v2;
#pragma unroll
    for (int o = 16; o; o >>= 1) s += __shfl_xor_sync(0xffffffffu, s, o);
    if ((t & 31) == 0) red[t >> 5] = s;
    __syncthreads();
    float tot = red[0]+red[1]+red[2]+red[3]+red[4]+red[5]+red[6]+red[7];
    float mu = tot * (1.f / CC);
    float d0 = v0 - mu, d1 = v1 - mu, d2 = v2 - mu;
    float q = d0*d0 + d1*d1 + d2*d2;
#pragma unroll
    for (int o = 16; o; o >>= 1) q += __shfl_xor_sync(0xffffffffu, q, o);
    __syncthreads();
    if ((t & 31) == 0) red[t >> 5] = q;
    __syncthreads();
    float var = (red[0]+red[1]+red[2]+red[3]+red[4]+red[5]+red[6]+red[7]) * (1.f / CC);
    float inv = rsqrtf(var + 1e-5f);
    out[base + t]       = (d0 * inv * lw[t]       + lb[t])       * g[base + t];
    out[base + t + 256] = (d1 * inv * lw[t + 256] + lb[t + 256]) * g[base + t + 256];
    out[base + t + 512] = (d2 * inv * lw[t + 512] + lb[t + 512]) * g[base + t + 512];
}

// ------------------------------- launcher -----------------------------------
extern "C" void kernel_launch(void* const* d_in, const int* in_sizes, int n_in,
                              void* d_out, int out_size)
{
    const float* x    = (const float*)d_in[0];
    const float* tmx  = (const float*)d_in[1];
    const float* tmw  = (const float*)d_in[2];
    const float* tmk  = (const float*)d_in[3];
    const float* tmv  = (const float*)d_in[4];
    const float* tmr  = (const float*)d_in[5];
    const float* tmg  = (const float*)d_in[6];
    const float* w1   = (const float*)d_in[7];   // (768,160)
    const float* w2   = (const float*)d_in[8];   // (5,32,768)
    const float* tdec = (const float*)d_in[9];   // (768)
    const float* dw1  = (const float*)d_in[10];  // (768,64)
    const float* dw2  = (const float*)d_in[11];  // (64,768)
    const float* faaa = (const float*)d_in[12];  // (24,32)
    const float* W_r  = (const float*)d_in[13];
    const float* W_k  = (const float*)d_in[14];
    const float* W_v  = (const float*)d_in[15];
    const float* W_g  = (const float*)d_in[16];
    const float* W_o  = (const float*)d_in[17];
    const float* lnw  = (const float*)d_in[18];
    const float* lnb  = (const float*)d_in[19];
    float* out = (float*)d_out;

    float* buf = nullptr;
    cudaGetSymbolAddress((void**)&buf, g_scratch);

    float* xx  = buf;
    float* xxx = buf + 1 * SSLOT;
    float* m0  = buf + 2 * SSLOT;   // -> xw
    float* m1  = buf + 3 * SSLOT;   // -> xk
    float* m2  = buf + 4 * SSLOT;   // -> xv
    float* m3  = buf + 5 * SSLOT;   // -> xr
    float* m4  = buf + 6 * SSLOT;   // -> xg
    float* rr  = buf + 7 * SSLOT;
    float* kk  = buf + 8 * SSLOT;
    float* vv  = buf + 9 * SSLOT;
    float* gg  = buf + 10 * SSLOT;
    float* eww = buf + 11 * SSLOT;  // exp(w)
    float* yy  = buf + 12 * SSLOT;
    float* G1  = buf + 13 * SSLOT;              // 4096 x 160
    float* ww  = buf + 13 * SSLOT + 1048576;    // 4096 x 64
    float* ln  = xx;                            // reuse xx for LN*g output

    // transposed weights
    float* Wt_r = buf + 14 * SSLOT;
    float* Wt_k = Wt_r + 589824;
    float* Wt_v = Wt_k + 589824;
    float* Wt_g = Wt_v + 589824;
    float* Wt_o = Wt_g + 589824;
    float* w1t  = Wt_o + 589824;        // 256 x 768
    float* dw1t = buf + 15 * SSLOT;     // 128 x 768
    float* dw2t = dw1t + 98304;         // 768 x 64
    float* w2t  = dw2t + 49152;         // 5 x 768 x 32

    const int EW4 = (MM * (CC/4) + 255) / 256;

    // 0) weight transposes + tf32 pre-round
    {
        TArgs ta = {};
        const float* srcs[NTR] = {W_r, W_k, W_v, W_g, W_o, w1, dw1, dw2,
                                  w2, w2 + 32*768, w2 + 2*32*768,
                                  w2 + 3*32*768, w2 + 4*32*768};
        float* dsts[NTR] = {Wt_r, Wt_k, Wt_v, Wt_g, Wt_o, w1t, dw1t, dw2t,
                            w2t, w2t + 24576, w2t + 2*24576,
                            w2t + 3*24576, w2t + 4*24576};
        int Ks[NTR]  = {768,768,768,768,768, 768, 768, 64, 32,32,32,32,32};
        int Ns[NTR]  = {768,768,768,768,768, 160,  64, 768, 768,768,768,768,768};
        int Nps[NTR] = {768,768,768,768,768, 256, 128, 768, 768,768,768,768,768};
        for (int i = 0; i < NTR; i++) {
            ta.src[i] = srcs[i]; ta.dst[i] = dsts[i];
            ta.K[i] = Ks[i]; ta.N[i] = Ns[i]; ta.Np[i] = Nps[i];
        }
        transpose_kernel<<<dim3(24, 24, NTR), dim3(32, 8)>>>(ta);
    }

    // 1) q-shift + maa_x mix
    shift_kernel<<<EW4, 256>>>(x, tmx, xx, xxx);

    // 2) G1 = tanh(xxx @ w1)
    {
        GArgs a = {};
        a.A[0] = xxx; a.B[0] = w1t; a.C[0] = G1;
        a.ep[0] = EP_TANH; a.N[0] = 160; a.lda[0] = CC; a.K = CC;
        gemm_kernel<<<dim3(2, 32, 1), 256>>>(a);
    }

    // 3) 5 mix GEMMs (K=32), fused mix epilogue
    {
        GArgs a = {};
        float* mouts[5] = {m0, m1, m2, m3, m4};
        const float* tms[5] = {tmw, tmk, tmv, tmr, tmg};
        for (int q = 0; q < 5; q++) {
            a.A[q] = G1 + q * 32;
            a.B[q] = w2t + (size_t)q * 24576;
            a.C[q] = mouts[q];
            a.tm[q] = tms[q];
            a.ep[q] = EP_MIX; a.N[q] = CC; a.lda[q] = 160;
        }
        a.K = 32; a.x = x; a.xx = xx;
        gemm_kernel<<<dim3(6, 32, 5), 256>>>(a);
    }

    // 4) grouped projections: r,k,v,g (N=768) + dw1 (N=64), K=768
    {
        GArgs a = {};
        a.A[0] = m3; a.B[0] = Wt_r; a.C[0] = rr; a.ep[0] = EP_NONE; a.N[0] = CC; a.lda[0] = CC;
        a.A[1] = m1; a.B[1] = Wt_k; a.C[1] = kk; a.ep[1] = EP_NONE; a.N[1] = CC; a.lda[1] = CC;
        a.A[2] = m2; a.B[2] = Wt_v; a.C[2] = vv; a.ep[2] = EP_NONE; a.N[2] = CC; a.lda[2] = CC;
        a.A[3] = m4; a.B[3] = Wt_g; a.C[3] = gg; a.ep[3] = EP_SILU; a.N[3] = CC; a.lda[3] = CC;
        a.A[4] = m0; a.B[4] = dw1t; a.C[4] = ww; a.ep[4] = EP_TANH; a.N[4] = 64; a.lda[4] = CC;
        a.K = CC;
        gemm_kernel<<<dim3(6, 32, 5), 256>>>(a);
    }

    // 5) eww = exp(tdec + ww @ dw2)
    {
        GArgs a = {};
        a.A[0] = ww; a.B[0] = dw2t; a.C[0] = eww;
        a.ep[0] = EP_EXPW; a.N[0] = CC; a.lda[0] = 64; a.K = 64;
        a.bias = tdec;
        gemm_kernel<<<dim3(6, 32, 1), 256>>>(a);
    }

    // 6) chunked WKV6
    wkv_chunk_kernel<<<BBATCH * NHD, 256>>>(rr, kk, vv, eww, faaa, yy);

    // 7) LayerNorm * gate
    ln_gate_kernel<<<MM, 256>>>(yy, gg, lnw, lnb, ln);

    // 8) output projection
    {
        GArgs a = {};
        a.A[0] = ln; a.B[0] = Wt_o; a.C[0] = out;
        a.ep[0] = EP_NONE; a.N[0] = CC; a.lda[0] = CC; a.K = CC;
        gemm_kernel<<<dim3(6, 32, 1), 256>>>(a);
    }

    (void)in_sizes; (void)n_in; (void)out_size;
}

// round 5
// speedup vs baseline: 3.0044x; 1.2122x over previous
#include <cuda_runtime.h>
#include <math.h>
#include <stdint.h>

// ----------------------------- problem constants ---------------------------
#define CC   768
#define TT   1024
#define BBATCH 4
#define MM   (BBATCH*TT)      // 4096 tokens
#define NHD  24
#define HSZ  32
#define HP_  32
#define WP_  32
#define C4   (CC/4)           // 192
#define CL   32               // wkv chunk length

#define SSLOT 3145728ull                   // 4096*768 floats
__device__ float g_scratch[16ull*SSLOT];

enum { EP_NONE = 0, EP_TANH = 1, EP_SILU = 2, EP_EXPW = 3, EP_MIX = 4 };

// ----------------------------- TF32 helpers --------------------------------
__device__ __forceinline__ float f2tf32(float x) {
    uint32_t r;
    asm("cvt.rna.tf32.f32 %0, %1;" : "=r"(r) : "f"(x));
    return __uint_as_float(r);
}

__device__ __forceinline__ void mma_tf32(float acc[4], const uint32_t a[4],
                                         const uint32_t b0, const uint32_t b1) {
    asm volatile(
        "mma.sync.aligned.m16n8k8.row.col.f32.tf32.tf32.f32 "
        "{%0,%1,%2,%3}, {%4,%5,%6,%7}, {%8,%9}, {%0,%1,%2,%3};"
        : "+f"(acc[0]), "+f"(acc[1]), "+f"(acc[2]), "+f"(acc[3])
        : "r"(a[0]), "r"(a[1]), "r"(a[2]), "r"(a[3]), "r"(b0), "r"(b1));
}

#define LDSM4(d0, d1, d2, d3, addr)                                           \
    asm volatile("ldmatrix.sync.aligned.m8n8.x4.shared.b16 {%0,%1,%2,%3}, [%4];" \
                 : "=r"(d0), "=r"(d1), "=r"(d2), "=r"(d3) : "r"(addr));

__device__ __forceinline__ void cpasync16(uint32_t saddr, const void* gptr) {
    asm volatile("cp.async.cg.shared.global [%0], [%1], 16;"
                 :: "r"(saddr), "l"(gptr));
}

// --------------------- weight transpose + tf32 pre-round --------------------
#define NTR 13
struct TArgs {
    const float* src[NTR];
    float*       dst[NTR];
    int K[NTR];
    int N[NTR];
    int Np[NTR];
};

__global__ void transpose_kernel(TArgs ta)
{
    __shared__ float tile[32][33];
    const int z = blockIdx.z;
    const int K = ta.K[z], N = ta.N[z], Np = ta.Np[z];
    const int x0 = blockIdx.x * 32;   // n
    const int y0 = blockIdx.y * 32;   // k
    if (x0 >= Np || y0 >= K) return;
    const float* src = ta.src[z];
    float* dst = ta.dst[z];
    const int tx = threadIdx.x, ty = threadIdx.y;
#pragma unroll
    for (int j = 0; j < 4; j++) {
        int k = y0 + ty + 8 * j;
        int n = x0 + tx;
        float v = (n < N) ? src[(size_t)k * N + n] : 0.f;
        tile[ty + 8 * j][tx] = f2tf32(v);
    }
    __syncthreads();
#pragma unroll
    for (int j = 0; j < 4; j++) {
        int n = x0 + ty + 8 * j;
        int k = y0 + tx;
        dst[(size_t)n * K + k] = tile[tx][ty + 8 * j];
    }
}

// -------------------------- grouped TF32 MMA GEMM ---------------------------
// Per z: C[M,N] = ep( A[M,K](lda) @ Bt[n][k]^T ). M%128==0, K%16==0.
// Bt pre-transposed + tf32-rounded: Bt[Np][K], Np multiple of 128.
struct GArgs {
    const float* A[5];
    const float* B[5];
    float*       C[5];
    const float* tm[5];
    int ep[5];
    int N[5];
    int lda[5];
    int K;
    const float* x;
    const float* xx;
    const float* bias;
};

#define TBM 128
#define TBN 128
#define TBK 16
#define STAGE_B 10240u          // bytes per stage per operand (128 rows * 80B)
#define GEMM_DSMEM 81920        // 4 stages * 2 operands * 10240

#define ISSUE_TILE(tile)                                                       \
    {                                                                          \
        int k0_ = (tile) * TBK;                                                \
        uint32_t sa_ = as_u + ((tile) & 3) * STAGE_B;                          \
        uint32_t sb_ = bs_u + ((tile) & 3) * STAGE_B;                          \
        int row_ = tid >> 2;                                                   \
        int chb_ = (tid & 3) * 16;                                             \
        int chf_ = (tid & 3) * 4;                                              \
        cpasync16(sa_ + row_ * 80 + chb_,                                      \
                  A + (size_t)(bm + row_) * lda + k0_ + chf_);                 \
        cpasync16(sa_ + (row_ + 64) * 80 + chb_,                               \
                  A + (size_t)(bm + row_ + 64) * lda + k0_ + chf_);            \
        cpasync16(sb_ + row_ * 80 + chb_,                                      \
                  B + (size_t)(bn + row_) * K + k0_ + chf_);                   \
        cpasync16(sb_ + (row_ + 64) * 80 + chb_,                               \
                  B + (size_t)(bn + row_ + 64) * K + k0_ + chf_);              \
        asm volatile("cp.async.commit_group;");                                \
    }

__global__ void __launch_bounds__(256, 2) gemm_kernel(GArgs ga)
{
    extern __shared__ float sdyn[];

    const int z = blockIdx.z;
    const float* __restrict__ A = ga.A[z];
    const float* __restrict__ B = ga.B[z];
    float* __restrict__ C = ga.C[z];
    const int N   = ga.N[z];
    const int lda = ga.lda[z];
    const int K   = ga.K;
    const int ep  = ga.ep[z];

    const int bn = blockIdx.x * TBN;
    if (bn >= N) return;
    const int bm = blockIdx.y * TBM;

    const int tid  = threadIdx.x;
    const int lane = tid & 31;
    const int wid  = tid >> 5;
    const int gr = lane >> 2, gc = lane & 3;
    const int wm = (wid & 3) * 32;
    const int wn = (wid >> 2) * 64;

    const uint32_t as_u = (uint32_t)__cvta_generic_to_shared(sdyn);
    const uint32_t bs_u = as_u + 4 * STAGE_B;

    // ldmatrix lane base addresses (within stage 0)
    const int p  = lane >> 3;
    const int pr = lane & 7;
    const uint32_t a_lane = as_u + (uint32_t)((wm + (p & 1) * 8 + pr) * 80 + (p >> 1) * 16);
    const uint32_t b_lane = bs_u + (uint32_t)((wn + (p >> 1) * 8 + pr) * 80 + (p & 1) * 16);

    float acc[2][8][4];
#pragma unroll
    for (int mi = 0; mi < 2; mi++)
#pragma unroll
        for (int ni = 0; ni < 8; ni++)
#pragma unroll
            for (int c = 0; c < 4; c++) acc[mi][ni][c] = 0.f;

    const int niter = K / TBK;

    // prologue: up to 3 tiles in flight
    ISSUE_TILE(0)
    if (niter > 1) ISSUE_TILE(1)
    if (niter > 2) ISSUE_TILE(2)

    for (int it = 0; it < niter; it++) {
        const int remafter = niter - it - 1;
        if (remafter >= 2)      asm volatile("cp.async.wait_group 2;");
        else if (remafter == 1) asm volatile("cp.async.wait_group 1;");
        else                    asm volatile("cp.async.wait_group 0;");
        __syncthreads();

        if (it + 3 < niter) ISSUE_TILE(it + 3)

        const uint32_t abase = a_lane + (uint32_t)(it & 3) * STAGE_B;
        const uint32_t bbase = b_lane + (uint32_t)(it & 3) * STAGE_B;
#pragma unroll
        for (int kk = 0; kk < TBK; kk += 8) {
            uint32_t af[2][4], bf[4][4];
#pragma unroll
            for (int mi = 0; mi < 2; mi++) {
                LDSM4(af[mi][0], af[mi][1], af[mi][2], af[mi][3],
                      abase + mi * 1280 + kk * 4)
#pragma unroll
                for (int q = 0; q < 4; q++)
                    asm("cvt.rna.tf32.f32 %0, %0;" : "+r"(af[mi][q]));
            }
#pragma unroll
            for (int P = 0; P < 4; P++)
                LDSM4(bf[P][0], bf[P][1], bf[P][2], bf[P][3],
                      bbase + P * 1280 + kk * 4)
#pragma unroll
            for (int mi = 0; mi < 2; mi++)
#pragma unroll
                for (int ni = 0; ni < 8; ni++)
                    mma_tf32(acc[mi][ni], af[mi],
                             bf[ni >> 1][(ni & 1) * 2],
                             bf[ni >> 1][(ni & 1) * 2 + 1]);
        }
        __syncthreads();
    }

    // ---------------- staged, coalesced epilogue ----------------
    // reuse pipeline smem as a 128 x 132 fp32 tile
    float* Cs = sdyn;
#pragma unroll
    for (int mi = 0; mi < 2; mi++)
#pragma unroll
        for (int ni = 0; ni < 8; ni++)
#pragma unroll
            for (int cp = 0; cp < 2; cp++) {
                int row = wm + mi * 16 + gr + cp * 8;
                int col = wn + ni * 8 + 2 * gc;
                *(float2*)&Cs[row * 132 + col] =
                    make_float2(acc[mi][ni][cp * 2], acc[mi][ni][cp * 2 + 1]);
            }
    __syncthreads();

    const float* tmv = ga.tm[z];
#pragma unroll
    for (int ps = 0; ps < 16; ps++) {
        int row  = ps * 8 + wid;
        int col  = lane * 4;
        int grow = bm + row;
        int gcol = bn + col;
        float4 v = *(float4*)&Cs[row * 132 + col];

        if (ep == EP_TANH) {
            v.x = tanhf(v.x); v.y = tanhf(v.y); v.z = tanhf(v.z); v.w = tanhf(v.w);
        } else if (ep == EP_SILU) {
            v.x = v.x / (1.f + expf(-v.x)); v.y = v.y / (1.f + expf(-v.y));
            v.z = v.z / (1.f + expf(-v.z)); v.w = v.w / (1.f + expf(-v.w));
        } else if (ep == EP_EXPW) {
            v.x = expf(ga.bias[gcol]     + v.x);
            v.y = expf(ga.bias[gcol + 1] + v.y);
            v.z = expf(ga.bias[gcol + 2] + v.z);
            v.w = expf(ga.bias[gcol + 3] + v.w);
        } else if (ep == EP_MIX) {
            size_t ix = (size_t)grow * CC + gcol;
            float4 x4  = *(const float4*)(ga.x + ix);
            float4 xx4 = *(const float4*)(ga.xx + ix);
            float4 t4  = *(const float4*)(tmv + gcol);
            v.x = fmaf(xx4.x, t4.x + v.x, x4.x);
            v.y = fmaf(xx4.y, t4.y + v.y, x4.y);
            v.z = fmaf(xx4.z, t4.z + v.z, x4.z);
            v.w = fmaf(xx4.w, t4.w + v.w, x4.w);
        }

        if (gcol + 3 < N) {
            *(float4*)&C[(size_t)grow * N + gcol] = v;
        } else if (gcol < N) {
            float vs[4] = {v.x, v.y, v.z, v.w};
            for (int e = 0; e < 4; e++)
                if (gcol + e < N) C[(size_t)grow * N + gcol + e] = vs[e];
        }
    }
}

// ------------------------- q_shift + maa_x mix (float4) ---------------------
__global__ void shift_kernel(const float* __restrict__ x,
                             const float* __restrict__ tmx,
                             float* __restrict__ xx,
                             float* __restrict__ xxx)
{
    int idx = blockIdx.x * blockDim.x + threadIdx.x;   // over MM*192
    if (idx >= MM * (CC/4)) return;
    int c4i = idx % (CC/4);
    int m   = idx / (CC/4);
    int c   = c4i * 4;
    int b = m >> 10;
    int t = m & 1023;
    int hh = t >> 5;
    int w  = t & 31;
    int q  = c / C4;
    int sh = hh + ((q == 2) ? -1 : (q == 3) ? 1 : 0);
    int sw = w  + ((q == 0) ? -1 : (q == 1) ? 1 : 0);
    float4 xs = make_float4(0.f, 0.f, 0.f, 0.f);
    if (sh >= 0 && sh < HP_ && sw >= 0 && sw < WP_)
        xs = *(const float4*)(x + ((size_t)((b << 10) + (sh << 5) + sw)) * CC + c);
    float4 xv = ((const float4*)x)[idx];
    float4 tm = *(const float4*)(tmx + c);
    float4 d, o;
    d.x = xs.x - xv.x; d.y = xs.y - xv.y; d.z = xs.z - xv.z; d.w = xs.w - xv.w;
    o.x = fmaf(d.x, tm.x, xv.x); o.y = fmaf(d.y, tm.y, xv.y);
    o.z = fmaf(d.z, tm.z, xv.z); o.w = fmaf(d.w, tm.w, xv.w);
    ((float4*)xx)[idx]  = d;
    ((float4*)xxx)[idx] = o;
}

// ----------------------------- chunked WKV6 ---------------------------------
__global__ void __launch_bounds__(256) wkv_chunk_kernel(
    const float* __restrict__ r, const float* __restrict__ k,
    const float* __restrict__ v, const float* __restrict__ ew,
    const float* __restrict__ u, float* __restrict__ y)
{
    __shared__ float sr[CL][36], sk[CL][36], sv[CL][36], se[CL][36];
    __shared__ float scum[CL][36], sKtT[HSZ][36], satt[CL][36], sS[HSZ][36];
    __shared__ float sdiag[CL], scend[HSZ], su[HSZ];

    const int head = blockIdx.x;
    const int b = head / NHD, h = head % NHD;
    const int tid  = threadIdx.x;
    const int lane = tid & 31;
    const int wid  = tid >> 5;
    const int tld = tid >> 3;
    const int jld = (tid & 7) << 2;

    if (tid < HSZ) su[tid] = u[h * HSZ + tid];
    for (int zz = tid; zz < HSZ * 36; zz += 256) ((float*)sS)[zz] = 0.f;

    const size_t base = (size_t)b * TT * CC + (size_t)h * HSZ;

    size_t g0 = base + (size_t)tld * CC + jld;
    float4 r4 = *(const float4*)(r  + g0);
    float4 k4 = *(const float4*)(k  + g0);
    float4 v4 = *(const float4*)(v  + g0);
    float4 e4 = *(const float4*)(ew + g0);
    __syncthreads();

    for (int c0 = 0; c0 < TT; c0 += CL) {
        *(float4*)&sr[tld][jld] = r4;
        *(float4*)&sk[tld][jld] = k4;
        *(float4*)&sv[tld][jld] = v4;
        *(float4*)&se[tld][jld] = e4;
        __syncthreads();

#pragma unroll
        for (int q = 0; q < 4; q++) {
            int j = wid * 4 + q;
            float vv = se[lane][j];
#pragma unroll
            for (int off = 1; off < 32; off <<= 1) {
                float nb = __shfl_up_sync(0xffffffffu, vv, off);
                if (lane >= off) vv += nb;
            }
            scum[lane][j] = vv;
            if (lane == 31) scend[j] = vv;
        }
        {
            float pp = 0.f;
#pragma unroll
            for (int e = 0; e < 4; e++)
                pp += sr[tld][jld + e] * su[jld + e] * sk[tld][jld + e];
            pp += __shfl_xor_sync(0xffffffffu, pp, 1);
            pp += __shfl_xor_sync(0xffffffffu, pp, 2);
            pp += __shfl_xor_sync(0xffffffffu, pp, 4);
            if ((lane & 7) == 0) sdiag[tld] = pp;
        }
        __syncthreads();

#pragma unroll
        for (int e = 0; e < 4; e++) {
            int j = jld + e;
            float cum = scum[tld][j];
            float ev  = se[tld][j];
            float rw  = sr[tld][j];
            float kw  = sk[tld][j];
            sr[tld][j]   = rw * expf(ev - cum);
            sKtT[j][tld] = kw * expf(cum);
            scum[tld][j] = kw * expf(cum - scend[j]);
        }
        __syncthreads();

        {
            const int t = tld, t4 = jld;
            float a0 = 0.f, a1 = 0.f, a2 = 0.f, a3 = 0.f;
#pragma unroll
            for (int j = 0; j < HSZ; j++) {
                float rt = sr[t][j];
                float4 kt = *(const float4*)&sKtT[j][t4];
                a0 = fmaf(rt, kt.x, a0); a1 = fmaf(rt, kt.y, a1);
                a2 = fmaf(rt, kt.z, a2); a3 = fmaf(rt, kt.w, a3);
            }
            float dv = sdiag[t];
            satt[t][t4+0] = (t4+0 < t) ? a0 : ((t4+0 == t) ? dv : 0.f);
            satt[t][t4+1] = (t4+1 < t) ? a1 : ((t4+1 == t) ? dv : 0.f);
            satt[t][t4+2] = (t4+2 < t) ? a2 : ((t4+2 == t) ? dv : 0.f);
            satt[t][t4+3] = (t4+3 < t) ? a3 : ((t4+3 == t) ? dv : 0.f);
        }
        __syncthreads();

        if (c0 + CL < TT) {
            size_t gn = base + (size_t)(c0 + CL + tld) * CC + jld;
            r4 = *(const float4*)(r  + gn);
            k4 = *(const float4*)(k  + gn);
            v4 = *(const float4*)(v  + gn);
            e4 = *(const float4*)(ew + gn);
        }

        {
            const int t = tld, i4 = jld;
            float4 acc = make_float4(0.f, 0.f, 0.f, 0.f);
#pragma unroll
            for (int tau = 0; tau < CL; tau++) {
                float at = satt[t][tau];
                float4 vv = *(const float4*)&sv[tau][i4];
                acc.x = fmaf(at, vv.x, acc.x); acc.y = fmaf(at, vv.y, acc.y);
                acc.z = fmaf(at, vv.z, acc.z); acc.w = fmaf(at, vv.w, acc.w);
            }
#pragma unroll
            for (int j = 0; j < HSZ; j++) {
                float rt = sr[t][j];
                float4 sj = *(const float4*)&sS[j][i4];
                acc.x = fmaf(rt, sj.x, acc.x); acc.y = fmaf(rt, sj.y, acc.y);
                acc.z = fmaf(rt, sj.z, acc.z); acc.w = fmaf(rt, sj.w, acc.w);
            }
            *(float4*)(y + base + (size_t)(c0 + t) * CC + i4) = acc;
        }
        __syncthreads();

        {
            const int j = tld, i4 = jld;
            float dend = expf(-scend[j]);
            float4 s = *(const float4*)&sS[j][i4];
            s.x *= dend; s.y *= dend; s.z *= dend; s.w *= dend;
#pragma unroll
            for (int tau = 0; tau < CL; tau++) {
                float kh = scum[tau][j];
                float4 vv = *(const float4*)&sv[tau][i4];
                s.x = fmaf(kh, vv.x, s.x); s.y = fmaf(kh, vv.y, s.y);
                s.z = fmaf(kh, vv.z, s.z); s.w = fmaf(kh, vv.w, s.w);
            }
            *(float4*)&sS[j][i4] = s;
        }
        __syncthreads();
    }
}

// --------------------------- LayerNorm * gate -------------------------------
__global__ void __launch_bounds__(256) ln_gate_kernel(
    const float* __restrict__ y, const float* __restrict__ g,
    const float* __restrict__ lw, const float* __restrict__ lb,
    float* __restrict__ out)
{
    __shared__ float red[8];
    int m = blockIdx.x;
    int t = threadIdx.x;
    size_t base = (size_t)m * CC;
    float v0 = y[base + t], v1 = y[base + t + 256], v2 = y[base + t + 512];
    float s = v0 + v1 + v2;
#pragma unroll
    for (int o = 16; o; o >>= 1) s += __shfl_xor_sync(0xffffffffu, s, o);
    if ((t & 31) == 0) red[t >> 5] = s;
    __syncthreads();
    float tot = red[0]+red[1]+red[2]+red[3]+red[4]+red[5]+red[6]+red[7];
    float mu = tot * (1.f / CC);
    float d0 = v0 - mu, d1 = v1 - mu, d2 = v2 - mu;
    float q = d0*d0 + d1*d1 + d2*d2;
#pragma unroll
    for (int o = 16; o; o >>= 1) q += __shfl_xor_sync(0xffffffffu, q, o);
    __syncthreads();
    if ((t & 31) == 0) red[t >> 5] = q;
    __syncthreads();
    float var = (red[0]+red[1]+red[2]+red[3]+red[4]+red[5]+red[6]+red[7]) * (1.f / CC);
    float inv = rsqrtf(var + 1e-5f);
    out[base + t]       = (d0 * inv * lw[t]       + lb[t])       * g[base + t];
    out[base + t + 256] = (d1 * inv * lw[t + 256] + lb[t + 256]) * g[base + t + 256];
    out[base + t + 512] = (d2 * inv * lw[t + 512] + lb[t + 512]) * g[base + t + 512];
}

// ------------------------------- launcher -----------------------------------
extern "C" void kernel_launch(void* const* d_in, const int* in_sizes, int n_in,
                              void* d_out, int out_size)
{
    const float* x    = (const float*)d_in[0];
    const float* tmx  = (const float*)d_in[1];
    const float* tmw  = (const float*)d_in[2];
    const float* tmk  = (const float*)d_in[3];
    const float* tmv  = (const float*)d_in[4];
    const float* tmr  = (const float*)d_in[5];
    const float* tmg  = (const float*)d_in[6];
    const float* w1   = (const float*)d_in[7];
    const float* w2   = (const float*)d_in[8];
    const float* tdec = (const float*)d_in[9];
    const float* dw1  = (const float*)d_in[10];
    const float* dw2  = (const float*)d_in[11];
    const float* faaa = (const float*)d_in[12];
    const float* W_r  = (const float*)d_in[13];
    const float* W_k  = (const float*)d_in[14];
    const float* W_v  = (const float*)d_in[15];
    const float* W_g  = (const float*)d_in[16];
    const float* W_o  = (const float*)d_in[17];
    const float* lnw  = (const float*)d_in[18];
    const float* lnb  = (const float*)d_in[19];
    float* out = (float*)d_out;

    static int smem_set = 0;
    if (!smem_set) {
        cudaFuncSetAttribute(gemm_kernel,
                             cudaFuncAttributeMaxDynamicSharedMemorySize,
                             GEMM_DSMEM);
        smem_set = 1;
    }

    float* buf = nullptr;
    cudaGetSymbolAddress((void**)&buf, g_scratch);

    float* xx  = buf;
    float* xxx = buf + 1 * SSLOT;
    float* m0  = buf + 2 * SSLOT;
    float* m1  = buf + 3 * SSLOT;
    float* m2  = buf + 4 * SSLOT;
    float* m3  = buf + 5 * SSLOT;
    float* m4  = buf + 6 * SSLOT;
    float* rr  = buf + 7 * SSLOT;
    float* kk  = buf + 8 * SSLOT;
    float* vv  = buf + 9 * SSLOT;
    float* gg  = buf + 10 * SSLOT;
    float* eww = buf + 11 * SSLOT;
    float* yy  = buf + 12 * SSLOT;
    float* G1  = buf + 13 * SSLOT;
    float* ww  = buf + 13 * SSLOT + 1048576;
    float* ln  = xx;

    float* Wt_r = buf + 14 * SSLOT;
    float* Wt_k = Wt_r + 589824;
    float* Wt_v = Wt_k + 589824;
    float* Wt_g = Wt_v + 589824;
    float* Wt_o = Wt_g + 589824;
    float* w1t  = Wt_o + 589824;
    float* dw1t = buf + 15 * SSLOT;
    float* dw2t = dw1t + 98304;
    float* w2t  = dw2t + 49152;

    const int EW4 = (MM * (CC/4) + 255) / 256;

    // 0) weight transposes + tf32 pre-round
    {
        TArgs ta = {};
        const float* srcs[NTR] = {W_r, W_k, W_v, W_g, W_o, w1, dw1, dw2,
                                  w2, w2 + 32*768, w2 + 2*32*768,
                                  w2 + 3*32*768, w2 + 4*32*768};
        float* dsts[NTR] = {Wt_r, Wt_k, Wt_v, Wt_g, Wt_o, w1t, dw1t, dw2t,
                            w2t, w2t + 24576, w2t + 2*24576,
                            w2t + 3*24576, w2t + 4*24576};
        int Ks[NTR]  = {768,768,768,768,768, 768, 768, 64, 32,32,32,32,32};
        int Ns[NTR]  = {768,768,768,768,768, 160,  64, 768, 768,768,768,768,768};
        int Nps[NTR] = {768,768,768,768,768, 256, 128, 768, 768,768,768,768,768};
        for (int i = 0; i < NTR; i++) {
            ta.src[i] = srcs[i]; ta.dst[i] = dsts[i];
            ta.K[i] = Ks[i]; ta.N[i] = Ns[i]; ta.Np[i] = Nps[i];
        }
        transpose_kernel<<<dim3(24, 24, NTR), dim3(32, 8)>>>(ta);
    }

    // 1) q-shift + maa_x mix
    shift_kernel<<<EW4, 256>>>(x, tmx, xx, xxx);

    // 2) G1 = tanh(xxx @ w1)
    {
        GArgs a = {};
        a.A[0] = xxx; a.B[0] = w1t; a.C[0] = G1;
        a.ep[0] = EP_TANH; a.N[0] = 160; a.lda[0] = CC; a.K = CC;
        gemm_kernel<<<dim3(2, 32, 1), 256, GEMM_DSMEM>>>(a);
    }

    // 3) 5 mix GEMMs (K=32), fused mix epilogue
    {
        GArgs a = {};
        float* mouts[5] = {m0, m1, m2, m3, m4};
        const float* tms[5] = {tmw, tmk, tmv, tmr, tmg};
        for (int q = 0; q < 5; q++) {
            a.A[q] = G1 + q * 32;
            a.B[q] = w2t + (size_t)q * 24576;
            a.C[q] = mouts[q];
            a.tm[q] = tms[q];
            a.ep[q] = EP_MIX; a.N[q] = CC; a.lda[q] = 160;
        }
        a.K = 32; a.x = x; a.xx = xx;
        gemm_kernel<<<dim3(6, 32, 5), 256, GEMM_DSMEM>>>(a);
    }

    // 4) grouped projections
    {
        GArgs a = {};
        a.A[0] = m3; a.B[0] = Wt_r; a.C[0] = rr; a.ep[0] = EP_NONE; a.N[0] = CC; a.lda[0] = CC;
        a.A[1] = m1; a.B[1] = Wt_k; a.C[1] = kk; a.ep[1] = EP_NONE; a.N[1] = CC; a.lda[1] = CC;
        a.A[2] = m2; a.B[2] = Wt_v; a.C[2] = vv; a.ep[2] = EP_NONE; a.N[2] = CC; a.lda[2] = CC;
        a.A[3] = m4; a.B[3] = Wt_g; a.C[3] = gg; a.ep[3] = EP_SILU; a.N[3] = CC; a.lda[3] = CC;
        a.A[4] = m0; a.B[4] = dw1t; a.C[4] = ww; a.ep[4] = EP_TANH; a.N[4] = 64; a.lda[4] = CC;
        a.K = CC;
        gemm_kernel<<<dim3(6, 32, 5), 256, GEMM_DSMEM>>>(a);
    }

    // 5) eww = exp(tdec + ww @ dw2)
    {
        GArgs a = {};
        a.A[0] = ww; a.B[0] = dw2t; a.C[0] = eww;
        a.ep[0] = EP_EXPW; a.N[0] = CC; a.lda[0] = 64; a.K = 64;
        a.bias = tdec;
        gemm_kernel<<<dim3(6, 32, 1), 256, GEMM_DSMEM>>>(a);
    }

    // 6) chunked WKV6
    wkv_chunk_kernel<<<BBATCH * NHD, 256>>>(rr, kk, vv, eww, faaa, yy);

    // 7) LayerNorm * gate
    ln_gate_kernel<<<MM, 256>>>(yy, gg, lnw, lnb, ln);

    // 8) output projection
    {
        GArgs a = {};
        a.A[0] = ln; a.B[0] = Wt_o; a.C[0] = out;
        a.ep[0] = EP_NONE; a.N[0] = CC; a.lda[0] = CC; a.K = CC;
        gemm_kernel<<<dim3(6, 32, 1), 256, GEMM_DSMEM>>>(a);
    }

    (void)in_sizes; (void)n_in; (void)out_size;
}